// round 7
// baseline (speedup 1.0000x reference)
#include <cuda_runtime.h>
#include <cuda_bf16.h>
#include <math.h>
#include <stdint.h>

// Problem constants (B=64, H=W=56, C=128)
#define BB 64
#define HH 56
#define WW 56
#define CC 128
#define LL (HH*WW)            // 3136
#define MM (BB*LL)            // 200704
#define HID 512
#define FWLD 260

typedef __nv_bfloat16 bf16;
typedef __nv_bfloat162 bf162;

// ---------------- scratch ----------------
__device__ bf16  g_y[(size_t)MM*CC];
__device__ bf16  g_q[(size_t)MM*CC];
__device__ bf16  g_c0[(size_t)MM*CC];
__device__ bf16  g_c1[(size_t)MM*CC];
__device__ bf16  g_call[(size_t)MM*CC];
__device__ bf16  g_y2[(size_t)MM*CC];
__device__ bf16  g_c2[(size_t)MM*CC];
__device__ bf16  g_hid[(size_t)MM*HID];
__device__ float g_gates[(size_t)MM*4];
__device__ float g_pool[BB*CC];
__device__ float g_p2[BB*CC];
__device__ float g_x1[(size_t)MM*CC];
__device__ bf16  g_wt[196608];             // packed bf16 weights, [N][K]

#define WT_QC   0        // [256,128]  (q then ctx)
#define WT_H    32768    // [128,128]
#define WT_PROJ 49152    // [128,128]
#define WT_FC1  65536    // [512,128]
#define WT_FC2  131072   // [128,512]

__device__ __forceinline__ float gelu_f(float x) {
    float y = 0.7978845608028654f * (x + 0.044715f * x * x * x);
    float t; asm("tanh.approx.f32 %0, %1;" : "=f"(t) : "f"(y));
    return 0.5f * x * (1.0f + t);
}
__device__ __forceinline__ uint32_t smem_u32(const void* p) {
    uint32_t a;
    asm("{ .reg .u64 t; cvta.to.shared.u64 t, %1; cvt.u32.u64 %0, t; }" : "=r"(a) : "l"(p));
    return a;
}
__device__ __forceinline__ void cp16(uint32_t dst, const void* src) {
    asm volatile("cp.async.cg.shared.global [%0], [%1], 16;" :: "r"(dst), "l"(src));
}
__device__ __forceinline__ void mma_bf16(float* d, const uint32_t* a, const uint32_t* b) {
    asm volatile(
        "mma.sync.aligned.m16n8k16.row.col.f32.bf16.bf16.f32 "
        "{%0,%1,%2,%3}, {%4,%5,%6,%7}, {%8,%9}, {%0,%1,%2,%3};"
        : "+f"(d[0]), "+f"(d[1]), "+f"(d[2]), "+f"(d[3])
        : "r"(a[0]), "r"(a[1]), "r"(a[2]), "r"(a[3]), "r"(b[0]), "r"(b[1]));
}

// ======== bf16 mma.sync GEMM: C[M,N] = epi(A[M,K] @ Bt[N,K]^T + bias) ========
// grid (M/128, N/128), 256 threads (8 warps 2x4), warp tile 64x32, BK=32.
// EPI: 0 none->bf16, 1 gelu->bf16, 2 *extra(bf16)->bf16, 3 +extra(f32)->f32,
//      4 dual bf16 out (n0==0 -> Cp, else -> extrap),
//      5 modulator: (+ g3[m]*P2[b,n]) * extra(bf16) -> bf16.
template<int EPI>
__global__ void __launch_bounds__(256, 2)
bf_gemm(const bf16* __restrict__ A, int lda,
        const bf16* __restrict__ Bt,
        const float* __restrict__ bias,
        void* __restrict__ Cp, int ldc,
        const void* __restrict__ extrap, int lde,
        int K,
        const float* __restrict__ g3,
        const float* __restrict__ P2v)
{
    __shared__ uint32_t As2[2][128][20];   // 32 halves = 16 words + 4 pad
    __shared__ uint32_t Bs2[2][128][20];

    const int tid  = threadIdx.x;
    const int lane = tid & 31, warp = tid >> 5;
    const int row  = lane >> 2, col = lane & 3;
    const int wm   = (warp >> 2) * 64;
    const int wn   = (warp & 3) * 32;
    const int m0   = blockIdx.x * 128, n0 = blockIdx.y * 128;

    const uint32_t sA = smem_u32(As2), sB = smem_u32(Bs2);
    const bf16* Ab = A + (size_t)m0 * lda;
    const bf16* Bb = Bt + (size_t)n0 * K;

    float acc[4][4][4];
    #pragma unroll
    for (int i = 0; i < 4; i++)
        #pragma unroll
        for (int j = 0; j < 4; j++)
            #pragma unroll
            for (int r = 0; r < 4; r++) acc[i][j][r] = 0.0f;

    const int r_ld = tid >> 2, s_ld = tid & 3;   // 128 rows x 4 x 16B
    auto load_chunk = [&](int kc, int buf) {
        #pragma unroll
        for (int t = 0; t < 2; t++) {
            int r = r_ld + t * 64;
            cp16(sA + (uint32_t)((((buf * 128 + r) * 20) + s_ld * 4) * 4),
                 Ab + (size_t)r * lda + kc + s_ld * 8);
        }
        #pragma unroll
        for (int t = 0; t < 2; t++) {
            int r = r_ld + t * 64;
            cp16(sB + (uint32_t)((((buf * 128 + r) * 20) + s_ld * 4) * 4),
                 Bb + (size_t)r * K + kc + s_ld * 8);
        }
        asm volatile("cp.async.commit_group;" ::: "memory");
    };

    const int NC = K / 32;
    load_chunk(0, 0);

    for (int i = 0; i < NC; i++) {
        int b = i & 1;
        if (i + 1 < NC) {
            load_chunk((i + 1) * 32, b ^ 1);
            asm volatile("cp.async.wait_group 1;" ::: "memory");
        } else {
            asm volatile("cp.async.wait_group 0;" ::: "memory");
        }
        __syncthreads();

        #pragma unroll
        for (int kk = 0; kk < 2; kk++) {
            const int wo = kk * 8;
            uint32_t af[4][4], bfr[4][2];
            #pragma unroll
            for (int mt = 0; mt < 4; mt++) {
                int m = wm + mt * 16 + row;
                af[mt][0] = As2[b][m    ][wo + col    ];
                af[mt][1] = As2[b][m + 8][wo + col    ];
                af[mt][2] = As2[b][m    ][wo + col + 4];
                af[mt][3] = As2[b][m + 8][wo + col + 4];
            }
            #pragma unroll
            for (int nt = 0; nt < 4; nt++) {
                int n = wn + nt * 8 + row;
                bfr[nt][0] = Bs2[b][n][wo + col    ];
                bfr[nt][1] = Bs2[b][n][wo + col + 4];
            }
            #pragma unroll
            for (int mt = 0; mt < 4; mt++)
                #pragma unroll
                for (int nt = 0; nt < 4; nt++)
                    mma_bf16(acc[mt][nt], af[mt], bfr[nt]);
        }
        __syncthreads();
    }

    // -------- epilogue --------
    bf16*  Cb = (bf16*)Cp;
    float* Cf = (float*)Cp;
    const bf16*  Eb = (const bf16*)extrap;
    const float* Ef = (const float*)extrap;

    #pragma unroll
    for (int mt = 0; mt < 4; mt++) {
        #pragma unroll
        for (int nt = 0; nt < 4; nt++) {
            int m = m0 + wm + mt * 16 + row;
            int n = n0 + wn + nt * 8 + 2 * col;
            float2 bv = *(const float2*)(bias + n);
            #pragma unroll
            for (int half = 0; half < 2; half++) {
                int mg = m + half * 8;
                float2 o;
                o.x = acc[mt][nt][half * 2 + 0] + bv.x;
                o.y = acc[mt][nt][half * 2 + 1] + bv.y;
                if (EPI == 0) {
                    *(bf162*)(Cb + (size_t)mg * ldc + n) = __floats2bfloat162_rn(o.x, o.y);
                } else if (EPI == 1) {
                    o.x = gelu_f(o.x); o.y = gelu_f(o.y);
                    *(bf162*)(Cb + (size_t)mg * ldc + n) = __floats2bfloat162_rn(o.x, o.y);
                } else if (EPI == 2) {
                    float2 e = __bfloat1622float2(*(const bf162*)(Eb + (size_t)mg * lde + n));
                    o.x *= e.x; o.y *= e.y;
                    *(bf162*)(Cb + (size_t)mg * ldc + n) = __floats2bfloat162_rn(o.x, o.y);
                } else if (EPI == 3) {
                    float2 e = *(const float2*)(Ef + (size_t)mg * lde + n);
                    o.x += e.x; o.y += e.y;
                    *(float2*)(Cf + (size_t)mg * ldc + n) = o;
                } else if (EPI == 4) {
                    bf16* dst = (n0 == 0) ? Cb : (bf16*)const_cast<void*>(extrap);
                    int nl = n - n0;
                    *(bf162*)(dst + (size_t)mg * ldc + nl) = __floats2bfloat162_rn(o.x, o.y);
                } else {  // EPI == 5: modulator with fused global-ctx term
                    int bidx = mg / LL;
                    float gate = g3[(size_t)mg * 4 + 3];
                    float2 p2 = *(const float2*)(P2v + bidx * CC + n);
                    o.x += gate * p2.x; o.y += gate * p2.y;
                    float2 e = __bfloat1622float2(*(const bf162*)(Eb + (size_t)mg * lde + n));
                    o.x *= e.x; o.y *= e.y;
                    *(bf162*)(Cb + (size_t)mg * ldc + n) = __floats2bfloat162_rn(o.x, o.y);
                }
            }
        }
    }
}

// ------------- fused weight pack (transpose) to bf16 [N][K] -------------
__global__ void pack_all(const float* __restrict__ f_w, const float* __restrict__ h_w,
                         const float* __restrict__ proj_w, const float* __restrict__ fc1_w,
                         const float* __restrict__ fc2_w, bf16* __restrict__ wt)
{
    int idx = blockIdx.x * 256 + threadIdx.x;
    if (idx >= 196608) return;
    float v;
    if (idx < 32768) {
        int n = idx >> 7, k = idx & 127;
        v = f_w[k * FWLD + n];
    } else if (idx < 49152) {
        int j = idx - 32768; int n = j >> 7, k = j & 127;
        v = h_w[k * 128 + n];
    } else if (idx < 65536) {
        int j = idx - 49152; int n = j >> 7, k = j & 127;
        v = proj_w[k * 128 + n];
    } else if (idx < 131072) {
        int j = idx - 65536; int n = j >> 7, k = j & 127;
        v = fc1_w[k * 512 + n];
    } else {
        int j = idx - 131072; int n = j / 512, k = j % 512;
        v = fc2_w[k * 128 + n];
    }
    wt[idx] = __float2bfloat16(v);
}

// ---------------- LayerNorm (+optional fused gates GEMV), grid-stride ----------------
// one warp per token; GATES: also emit gates[tok,0..3] = y_f32 . fw[:,256+j] + fb
template<bool GATES>
__global__ void ln_kernel(const float* __restrict__ x,
                          const float* __restrict__ g,
                          const float* __restrict__ b,
                          bf16* __restrict__ y,
                          const float* __restrict__ fw,
                          const float* __restrict__ fb,
                          float* __restrict__ gates)
{
    const int lane = threadIdx.x & 31;
    const int gwarp = (blockIdx.x * blockDim.x + threadIdx.x) >> 5;
    const int nwarp = (gridDim.x * blockDim.x) >> 5;

    float4 gg = ((const float4*)g)[lane];
    float4 bb = ((const float4*)b)[lane];
    float w[4][4], fbs[4];
    if (GATES) {
        int k0 = lane * 4;
        #pragma unroll
        for (int c = 0; c < 4; c++)
            #pragma unroll
            for (int j = 0; j < 4; j++)
                w[c][j] = fw[(k0 + c) * FWLD + 256 + j];
        #pragma unroll
        for (int j = 0; j < 4; j++) fbs[j] = fb[256 + j];
    }

    for (int tok = gwarp; tok < MM; tok += nwarp) {
        float4 v = ((const float4*)(x + (size_t)tok * CC))[lane];
        float s = v.x + v.y + v.z + v.w;
        #pragma unroll
        for (int o = 16; o; o >>= 1) s += __shfl_xor_sync(0xffffffffu, s, o);
        float mu = s * (1.0f / CC);
        float dx = v.x - mu, dy = v.y - mu, dz = v.z - mu, dw = v.w - mu;
        float s2 = dx*dx + dy*dy + dz*dz + dw*dw;
        #pragma unroll
        for (int o = 16; o; o >>= 1) s2 += __shfl_xor_sync(0xffffffffu, s2, o);
        float r = rsqrtf(s2 * (1.0f / CC) + 1e-5f);
        float y0 = dx * r * gg.x + bb.x;
        float y1 = dy * r * gg.y + bb.y;
        float y2v = dz * r * gg.z + bb.z;
        float y3 = dw * r * gg.w + bb.w;
        bf162 p0 = __floats2bfloat162_rn(y0, y1);
        bf162 p1 = __floats2bfloat162_rn(y2v, y3);
        uint2 u;
        u.x = *(uint32_t*)&p0; u.y = *(uint32_t*)&p1;
        ((uint2*)(y + (size_t)tok * CC))[lane] = u;

        if (GATES) {
            float sg[4];
            #pragma unroll
            for (int j = 0; j < 4; j++) {
                sg[j] = y0 * w[0][j] + y1 * w[1][j] + y2v * w[2][j] + y3 * w[3][j];
                #pragma unroll
                for (int o = 16; o; o >>= 1) sg[j] += __shfl_xor_sync(0xffffffffu, sg[j], o);
            }
            if (lane == 0) {
                float4 gv = make_float4(sg[0] + fbs[0], sg[1] + fbs[1],
                                        sg[2] + fbs[2], sg[3] + fbs[3]);
                *(float4*)(gates + (size_t)tok * 4) = gv;
            }
        }
    }
}

// ---------------- depthwise conv (channel-pair vectorized, TW=14) ----------------
template<int KS, bool INIT>
__global__ void dwconv_kernel(const bf16* __restrict__ in,
                              const float* __restrict__ kern,
                              const float* __restrict__ gates,
                              bf16* __restrict__ out,
                              bf16* __restrict__ ctxall,
                              int gidx)
{
    constexpr int P = KS / 2, TW = 14, IW = TW + KS - 1;
    int cp = threadIdx.x;                     // channel pair 0..63
    int blk = blockIdx.x;                     // B*H*(W/TW) = B*H*4
    int wt = blk & 3;
    int rem = blk >> 2;
    int h = rem % HH;
    int b = rem / HH;
    int w0 = wt * TW;

    float2 kw[KS * KS];
    #pragma unroll
    for (int i = 0; i < KS * KS; i++)
        kw[i] = make_float2(kern[i * CC + 2 * cp], kern[i * CC + 2 * cp + 1]);

    float2 acc[TW];
    #pragma unroll
    for (int o = 0; o < TW; o++) acc[o] = make_float2(0.0f, 0.0f);

    const bf162* base = (const bf162*)in + (size_t)b * LL * 64 + cp;
    #pragma unroll
    for (int kh = 0; kh < KS; kh++) {
        int ih = h + kh - P;
        if (ih < 0 || ih >= HH) continue;
        float2 inv[IW];
        #pragma unroll
        for (int i = 0; i < IW; i++) {
            int iw = w0 - P + i;
            inv[i] = (iw >= 0 && iw < WW)
                   ? __bfloat1622float2(base[((size_t)ih * WW + iw) * 64])
                   : make_float2(0.0f, 0.0f);
        }
        #pragma unroll
        for (int kx = 0; kx < KS; kx++) {
            float2 wv = kw[kh * KS + kx];
            #pragma unroll
            for (int o = 0; o < TW; o++) {
                acc[o].x += inv[o + kx].x * wv.x;
                acc[o].y += inv[o + kx].y * wv.y;
            }
        }
    }
    size_t opix = (size_t)b * LL + (size_t)h * WW + w0;
    bf162* outp = (bf162*)out;
    bf162* cap  = (bf162*)ctxall;
    #pragma unroll
    for (int o = 0; o < TW; o++) {
        float vx = gelu_f(acc[o].x), vy = gelu_f(acc[o].y);
        outp[(opix + o) * 64 + cp] = __floats2bfloat162_rn(vx, vy);
        float gt = gates[(opix + o) * 4 + gidx];
        if (INIT) {
            cap[(opix + o) * 64 + cp] = __floats2bfloat162_rn(vx * gt, vy * gt);
        } else {
            float2 cur = __bfloat1622float2(cap[(opix + o) * 64 + cp]);
            cap[(opix + o) * 64 + cp] = __floats2bfloat162_rn(cur.x + vx * gt, cur.y + vy * gt);
        }
    }
}

// ---------------- global mean pool + gelu ----------------
__global__ void pool_kernel(const bf16* __restrict__ ctx, float* __restrict__ pool)
{
    __shared__ float sm[8][128];
    int b = blockIdx.x;
    int tid = threadIdx.x;
    int c = tid & 127, s = tid >> 7;
    const bf16* p = ctx + ((size_t)b * LL + (size_t)s * (LL / 8)) * CC + c;
    float acc = 0.0f;
    for (int i = 0; i < LL / 8; i++) acc += __bfloat162float(p[(size_t)i * CC]);
    sm[s][c] = acc;
    __syncthreads();
    if (s == 0) {
        float t = 0.0f;
        #pragma unroll
        for (int k = 0; k < 8; k++) t += sm[k][c];
        pool[b * CC + c] = gelu_f(t * (1.0f / LL));
    }
}

// ---------------- P2[b,n] = pool[b,:] @ h_w[:,n]  (fp32, tiny) ----------------
__global__ void p2_kernel(const float* __restrict__ pool,
                          const float* __restrict__ h_w,
                          float* __restrict__ P2)
{
    __shared__ float prow[128];
    int b = blockIdx.x, n = threadIdx.x;
    prow[n] = pool[b * CC + n];
    __syncthreads();
    float s = 0.0f;
    #pragma unroll 8
    for (int k = 0; k < CC; k++) s += prow[k] * h_w[k * CC + n];
    P2[b * CC + n] = s;
}

// ---------------- launch ----------------
extern "C" void kernel_launch(void* const* d_in, const int* in_sizes, int n_in,
                              void* d_out, int out_size)
{
    const float* x      = (const float*)d_in[0];
    const float* f_w    = (const float*)d_in[1];
    const float* f_b    = (const float*)d_in[2];
    const float* k0     = (const float*)d_in[3];
    const float* k1     = (const float*)d_in[4];
    const float* k2     = (const float*)d_in[5];
    const float* h_w    = (const float*)d_in[6];
    const float* h_b    = (const float*)d_in[7];
    const float* proj_w = (const float*)d_in[8];
    const float* proj_b = (const float*)d_in[9];
    const float* ln1_g  = (const float*)d_in[10];
    const float* ln1_b  = (const float*)d_in[11];
    const float* ln2_g  = (const float*)d_in[12];
    const float* ln2_b  = (const float*)d_in[13];
    const float* fc1_w  = (const float*)d_in[14];
    const float* fc1_b  = (const float*)d_in[15];
    const float* fc2_w  = (const float*)d_in[16];
    const float* fc2_b  = (const float*)d_in[17];
    float* out = (float*)d_out;

    bf16 *y, *q, *c0, *c1, *call, *y2, *c2, *hid, *wt;
    float *gts, *pl, *p2, *x1;
    cudaGetSymbolAddress((void**)&y,    g_y);
    cudaGetSymbolAddress((void**)&q,    g_q);
    cudaGetSymbolAddress((void**)&c0,   g_c0);
    cudaGetSymbolAddress((void**)&c1,   g_c1);
    cudaGetSymbolAddress((void**)&call, g_call);
    cudaGetSymbolAddress((void**)&y2,   g_y2);
    cudaGetSymbolAddress((void**)&c2,   g_c2);
    cudaGetSymbolAddress((void**)&hid,  g_hid);
    cudaGetSymbolAddress((void**)&gts,  g_gates);
    cudaGetSymbolAddress((void**)&pl,   g_pool);
    cudaGetSymbolAddress((void**)&p2,   g_p2);
    cudaGetSymbolAddress((void**)&x1,   g_x1);
    cudaGetSymbolAddress((void**)&wt,   g_wt);

    const int MBLK = MM / 128;                 // 1568
    dim3 g1(MBLK, 1), g2(MBLK, 2), g4(MBLK, 4);
    const int conv_grid = BB * HH * 4;         // 14336 (TW=14)

    // 1. pack weights
    pack_all<<<768, 256>>>(f_w, h_w, proj_w, fc1_w, fc2_w, wt);
    // 2. y = LN1(x) + fused gates
    ln_kernel<true><<<3136, 256>>>(x, ln1_g, ln1_b, y, f_w, f_b, gts);
    // 3. fused q|ctx GEMM (N=256)
    bf_gemm<4><<<g2, 256>>>(y, CC, wt + WT_QC, f_b, q, CC, c0, CC, CC, nullptr, nullptr);
    // 4-6. focal levels
    dwconv_kernel<3, true ><<<conv_grid, 64>>>(c0, k0, gts, c1, call, 0);
    dwconv_kernel<5, false><<<conv_grid, 64>>>(c1, k1, gts, c0, call, 1);
    dwconv_kernel<7, false><<<conv_grid, 64>>>(c0, k2, gts, c1, call, 2);
    // 7. pool = gelu(mean(ctx3))
    pool_kernel<<<BB, 1024>>>(c1, pl);
    // 8. P2 = pool @ h_w
    p2_kernel<<<BB, 128>>>(pl, h_w, p2);
    // 9. y2 = (ctxall @ h_w + h_b + gate3*P2) * q
    bf_gemm<5><<<g1, 256>>>(call, CC, wt + WT_H, h_b, y2, CC, q, CC, CC, gts, p2);
    // 10. x1 = x + (y2 @ proj_w + proj_b)   (fp32)
    bf_gemm<3><<<g1, 256>>>(y2, CC, wt + WT_PROJ, proj_b, x1, CC, x, CC, CC, nullptr, nullptr);
    // 11. c2 = LN2(x1)
    ln_kernel<false><<<3136, 256>>>(x1, ln2_g, ln2_b, c2, nullptr, nullptr, nullptr);
    // 12. hid = gelu(c2 @ fc1_w + fc1_b)
    bf_gemm<1><<<g4, 256>>>(c2, CC, wt + WT_FC1, fc1_b, hid, HID, nullptr, 0, CC, nullptr, nullptr);
    // 13. out = x1 + (hid @ fc2_w + fc2_b)   (fp32)
    bf_gemm<3><<<g1, 256>>>(hid, HID, wt + WT_FC2, fc2_b, out, CC, x1, CC, HID, nullptr, nullptr);
}

// round 8
// speedup vs baseline: 1.0785x; 1.0785x over previous
#include <cuda_runtime.h>
#include <cuda_bf16.h>
#include <math.h>
#include <stdint.h>

// Problem constants (B=64, H=W=56, C=128)
#define BB 64
#define HH 56
#define WW 56
#define CC 128
#define LL (HH*WW)            // 3136
#define MM (BB*LL)            // 200704
#define HID 512
#define FWLD 260

typedef __nv_bfloat16 bf16;
typedef __nv_bfloat162 bf162;

// ---------------- scratch ----------------
__device__ bf16  g_y[(size_t)MM*CC];
__device__ bf16  g_q[(size_t)MM*CC];
__device__ bf16  g_c0[(size_t)MM*CC];
__device__ bf16  g_c1[(size_t)MM*CC];
__device__ bf16  g_call[(size_t)MM*CC];
__device__ bf16  g_y2[(size_t)MM*CC];
__device__ bf16  g_c2[(size_t)MM*CC];
__device__ bf16  g_hid[(size_t)MM*HID];
__device__ float g_gates[(size_t)MM*4];
__device__ float g_pool[BB*CC];
__device__ float g_p2[BB*CC];
__device__ float g_x1[(size_t)MM*CC];
__device__ bf16  g_wt[196608];             // packed bf16 weights, [N][K]

#define WT_QC   0        // [256,128]  (q then ctx)
#define WT_H    32768    // [128,128]
#define WT_PROJ 49152    // [128,128]
#define WT_FC1  65536    // [512,128]
#define WT_FC2  131072   // [128,512]

__device__ __forceinline__ float gelu_f(float x) {
    float y = 0.7978845608028654f * (x + 0.044715f * x * x * x);
    float t; asm("tanh.approx.f32 %0, %1;" : "=f"(t) : "f"(y));
    return 0.5f * x * (1.0f + t);
}
__device__ __forceinline__ uint32_t smem_u32(const void* p) {
    uint32_t a;
    asm("{ .reg .u64 t; cvta.to.shared.u64 t, %1; cvt.u32.u64 %0, t; }" : "=r"(a) : "l"(p));
    return a;
}
__device__ __forceinline__ void cp16(uint32_t dst, const void* src) {
    asm volatile("cp.async.cg.shared.global [%0], [%1], 16;" :: "r"(dst), "l"(src));
}
__device__ __forceinline__ void mma_bf16(float* d, const uint32_t* a, const uint32_t* b) {
    asm volatile(
        "mma.sync.aligned.m16n8k16.row.col.f32.bf16.bf16.f32 "
        "{%0,%1,%2,%3}, {%4,%5,%6,%7}, {%8,%9}, {%0,%1,%2,%3};"
        : "+f"(d[0]), "+f"(d[1]), "+f"(d[2]), "+f"(d[3])
        : "r"(a[0]), "r"(a[1]), "r"(a[2]), "r"(a[3]), "r"(b[0]), "r"(b[1]));
}
__device__ __forceinline__ void ldsm_x4(uint32_t* d, uint32_t addr) {
    asm volatile("ldmatrix.sync.aligned.m8n8.x4.shared.b16 {%0,%1,%2,%3}, [%4];"
        : "=r"(d[0]), "=r"(d[1]), "=r"(d[2]), "=r"(d[3]) : "r"(addr));
}

// ======== bf16 mma.sync GEMM: C[M,N] = epi(A[M,K] @ Bt[N,K]^T + bias) ========
// grid (M/128, N/128), 256 threads (8 warps 2x4), warp tile 64x32, BK=32.
// Fragments via ldmatrix.x4 (conflict-free on the 20-word row stride).
// EPI: 0 none->bf16, 1 gelu->bf16, 2 *extra(bf16)->bf16, 3 +extra(f32)->f32,
//      4 dual bf16 out (n0==0 -> Cp, else -> extrap),
//      5 modulator: (+ g3[m]*P2[b,n]) * extra(bf16) -> bf16.
template<int EPI>
__global__ void __launch_bounds__(256, 2)
bf_gemm(const bf16* __restrict__ A, int lda,
        const bf16* __restrict__ Bt,
        const float* __restrict__ bias,
        void* __restrict__ Cp, int ldc,
        const void* __restrict__ extrap, int lde,
        int K,
        const float* __restrict__ g3,
        const float* __restrict__ P2v)
{
    __shared__ uint32_t As2[2][128][20];   // 32 halves = 16 words + 4 pad
    __shared__ uint32_t Bs2[2][128][20];

    const int tid  = threadIdx.x;
    const int lane = tid & 31, warp = tid >> 5;
    const int row  = lane >> 2, col = lane & 3;
    const int g8   = lane >> 3, r8 = lane & 7;   // ldmatrix groups
    const int wm   = (warp >> 2) * 64;
    const int wn   = (warp & 3) * 32;
    const int m0   = blockIdx.x * 128, n0 = blockIdx.y * 128;

    const uint32_t sA = smem_u32(As2), sB = smem_u32(Bs2);
    const bf16* Ab = A + (size_t)m0 * lda;
    const bf16* Bb = Bt + (size_t)n0 * K;

    float acc[4][4][4];
    #pragma unroll
    for (int i = 0; i < 4; i++)
        #pragma unroll
        for (int j = 0; j < 4; j++)
            #pragma unroll
            for (int r = 0; r < 4; r++) acc[i][j][r] = 0.0f;

    const int r_ld = tid >> 2, s_ld = tid & 3;   // 128 rows x 4 x 16B
    auto load_chunk = [&](int kc, int buf) {
        #pragma unroll
        for (int t = 0; t < 2; t++) {
            int r = r_ld + t * 64;
            cp16(sA + (uint32_t)((((buf * 128 + r) * 20) + s_ld * 4) * 4),
                 Ab + (size_t)r * lda + kc + s_ld * 8);
        }
        #pragma unroll
        for (int t = 0; t < 2; t++) {
            int r = r_ld + t * 64;
            cp16(sB + (uint32_t)((((buf * 128 + r) * 20) + s_ld * 4) * 4),
                 Bb + (size_t)r * K + kc + s_ld * 8);
        }
        asm volatile("cp.async.commit_group;" ::: "memory");
    };

    const int NC = K / 32;
    load_chunk(0, 0);

    for (int i = 0; i < NC; i++) {
        int b = i & 1;
        if (i + 1 < NC) {
            load_chunk((i + 1) * 32, b ^ 1);
            asm volatile("cp.async.wait_group 1;" ::: "memory");
        } else {
            asm volatile("cp.async.wait_group 0;" ::: "memory");
        }
        __syncthreads();

        #pragma unroll
        for (int kk = 0; kk < 2; kk++) {
            const int wo = kk * 8;
            uint32_t af[4][4], bq[2][4];
            // A: one ldmatrix.x4 per 16x16 tile
            #pragma unroll
            for (int mt = 0; mt < 4; mt++) {
                int ar = wm + mt * 16 + (g8 & 1) * 8 + r8;
                uint32_t addr = sA + (uint32_t)((((b * 128 + ar) * 20) + wo + (g8 >> 1) * 4) * 4);
                ldsm_x4(af[mt], addr);
            }
            // B: one ldmatrix.x4 per PAIR of n8 tiles
            #pragma unroll
            for (int p = 0; p < 2; p++) {
                int br = wn + p * 16 + (g8 >> 1) * 8 + r8;
                uint32_t addr = sB + (uint32_t)((((b * 128 + br) * 20) + wo + (g8 & 1) * 4) * 4);
                ldsm_x4(bq[p], addr);
            }
            #pragma unroll
            for (int mt = 0; mt < 4; mt++)
                #pragma unroll
                for (int nt = 0; nt < 4; nt++)
                    mma_bf16(acc[mt][nt], af[mt], &bq[nt >> 1][(nt & 1) * 2]);
        }
        __syncthreads();
    }

    // -------- epilogue --------
    bf16*  Cb = (bf16*)Cp;
    float* Cf = (float*)Cp;
    const bf16*  Eb = (const bf16*)extrap;
    const float* Ef = (const float*)extrap;

    #pragma unroll
    for (int mt = 0; mt < 4; mt++) {
        #pragma unroll
        for (int nt = 0; nt < 4; nt++) {
            int m = m0 + wm + mt * 16 + row;
            int n = n0 + wn + nt * 8 + 2 * col;
            float2 bv = *(const float2*)(bias + n);
            #pragma unroll
            for (int half = 0; half < 2; half++) {
                int mg = m + half * 8;
                float2 o;
                o.x = acc[mt][nt][half * 2 + 0] + bv.x;
                o.y = acc[mt][nt][half * 2 + 1] + bv.y;
                if (EPI == 0) {
                    *(bf162*)(Cb + (size_t)mg * ldc + n) = __floats2bfloat162_rn(o.x, o.y);
                } else if (EPI == 1) {
                    o.x = gelu_f(o.x); o.y = gelu_f(o.y);
                    *(bf162*)(Cb + (size_t)mg * ldc + n) = __floats2bfloat162_rn(o.x, o.y);
                } else if (EPI == 2) {
                    float2 e = __bfloat1622float2(*(const bf162*)(Eb + (size_t)mg * lde + n));
                    o.x *= e.x; o.y *= e.y;
                    *(bf162*)(Cb + (size_t)mg * ldc + n) = __floats2bfloat162_rn(o.x, o.y);
                } else if (EPI == 3) {
                    float2 e = *(const float2*)(Ef + (size_t)mg * lde + n);
                    o.x += e.x; o.y += e.y;
                    *(float2*)(Cf + (size_t)mg * ldc + n) = o;
                } else if (EPI == 4) {
                    bf16* dst = (n0 == 0) ? Cb : (bf16*)const_cast<void*>(extrap);
                    int nl = n - n0;
                    *(bf162*)(dst + (size_t)mg * ldc + nl) = __floats2bfloat162_rn(o.x, o.y);
                } else {  // EPI == 5
                    int bidx = mg / LL;
                    float gate = g3[(size_t)mg * 4 + 3];
                    float2 p2 = *(const float2*)(P2v + bidx * CC + n);
                    o.x += gate * p2.x; o.y += gate * p2.y;
                    float2 e = __bfloat1622float2(*(const bf162*)(Eb + (size_t)mg * lde + n));
                    o.x *= e.x; o.y *= e.y;
                    *(bf162*)(Cb + (size_t)mg * ldc + n) = __floats2bfloat162_rn(o.x, o.y);
                }
            }
        }
    }
}

// ------------- fused weight pack (transpose) to bf16 [N][K] -------------
__global__ void pack_all(const float* __restrict__ f_w, const float* __restrict__ h_w,
                         const float* __restrict__ proj_w, const float* __restrict__ fc1_w,
                         const float* __restrict__ fc2_w, bf16* __restrict__ wt)
{
    int idx = blockIdx.x * 256 + threadIdx.x;
    if (idx >= 196608) return;
    float v;
    if (idx < 32768) {
        int n = idx >> 7, k = idx & 127;
        v = f_w[k * FWLD + n];
    } else if (idx < 49152) {
        int j = idx - 32768; int n = j >> 7, k = j & 127;
        v = h_w[k * 128 + n];
    } else if (idx < 65536) {
        int j = idx - 49152; int n = j >> 7, k = j & 127;
        v = proj_w[k * 128 + n];
    } else if (idx < 131072) {
        int j = idx - 65536; int n = j >> 7, k = j & 127;
        v = fc1_w[k * 512 + n];
    } else {
        int j = idx - 131072; int n = j / 512, k = j % 512;
        v = fc2_w[k * 128 + n];
    }
    wt[idx] = __float2bfloat16(v);
}

// ---------------- LayerNorm (+optional fused gates GEMV), grid-stride ----------------
template<bool GATES>
__global__ void ln_kernel(const float* __restrict__ x,
                          const float* __restrict__ g,
                          const float* __restrict__ b,
                          bf16* __restrict__ y,
                          const float* __restrict__ fw,
                          const float* __restrict__ fb,
                          float* __restrict__ gates)
{
    const int lane = threadIdx.x & 31;
    const int gwarp = (blockIdx.x * blockDim.x + threadIdx.x) >> 5;
    const int nwarp = (gridDim.x * blockDim.x) >> 5;

    float4 gg = ((const float4*)g)[lane];
    float4 bb = ((const float4*)b)[lane];
    float w[4][4], fbs[4];
    if (GATES) {
        int k0 = lane * 4;
        #pragma unroll
        for (int c = 0; c < 4; c++)
            #pragma unroll
            for (int j = 0; j < 4; j++)
                w[c][j] = fw[(k0 + c) * FWLD + 256 + j];
        #pragma unroll
        for (int j = 0; j < 4; j++) fbs[j] = fb[256 + j];
    }

    for (int tok = gwarp; tok < MM; tok += nwarp) {
        float4 v = ((const float4*)(x + (size_t)tok * CC))[lane];
        float s = v.x + v.y + v.z + v.w;
        #pragma unroll
        for (int o = 16; o; o >>= 1) s += __shfl_xor_sync(0xffffffffu, s, o);
        float mu = s * (1.0f / CC);
        float dx = v.x - mu, dy = v.y - mu, dz = v.z - mu, dw = v.w - mu;
        float s2 = dx*dx + dy*dy + dz*dz + dw*dw;
        #pragma unroll
        for (int o = 16; o; o >>= 1) s2 += __shfl_xor_sync(0xffffffffu, s2, o);
        float r = rsqrtf(s2 * (1.0f / CC) + 1e-5f);
        float y0 = dx * r * gg.x + bb.x;
        float y1 = dy * r * gg.y + bb.y;
        float y2v = dz * r * gg.z + bb.z;
        float y3 = dw * r * gg.w + bb.w;
        bf162 p0 = __floats2bfloat162_rn(y0, y1);
        bf162 p1 = __floats2bfloat162_rn(y2v, y3);
        uint2 u;
        u.x = *(uint32_t*)&p0; u.y = *(uint32_t*)&p1;
        ((uint2*)(y + (size_t)tok * CC))[lane] = u;

        if (GATES) {
            float sg[4];
            #pragma unroll
            for (int j = 0; j < 4; j++) {
                sg[j] = y0 * w[0][j] + y1 * w[1][j] + y2v * w[2][j] + y3 * w[3][j];
                #pragma unroll
                for (int o = 16; o; o >>= 1) sg[j] += __shfl_xor_sync(0xffffffffu, sg[j], o);
            }
            if (lane == 0) {
                float4 gv = make_float4(sg[0] + fbs[0], sg[1] + fbs[1],
                                        sg[2] + fbs[2], sg[3] + fbs[3]);
                *(float4*)(gates + (size_t)tok * 4) = gv;
            }
        }
    }
}

// ---------------- depthwise conv (channel-pair vectorized, TW=8) ----------------
template<int KS, bool INIT>
__global__ void dwconv_kernel(const bf16* __restrict__ in,
                              const float* __restrict__ kern,
                              const float* __restrict__ gates,
                              bf16* __restrict__ out,
                              bf16* __restrict__ ctxall,
                              int gidx)
{
    constexpr int P = KS / 2, TW = 8, IW = TW + KS - 1;
    int cp = threadIdx.x;                     // channel pair 0..63
    int blk = blockIdx.x;                     // B*H*(W/TW)
    int wt = blk % (WW / TW);
    int rem = blk / (WW / TW);
    int h = rem % HH;
    int b = rem / HH;
    int w0 = wt * TW;

    float2 kw[KS * KS];
    #pragma unroll
    for (int i = 0; i < KS * KS; i++)
        kw[i] = make_float2(kern[i * CC + 2 * cp], kern[i * CC + 2 * cp + 1]);

    float2 acc[TW];
    #pragma unroll
    for (int o = 0; o < TW; o++) acc[o] = make_float2(0.0f, 0.0f);

    const bf162* base = (const bf162*)in + (size_t)b * LL * 64 + cp;
    #pragma unroll
    for (int kh = 0; kh < KS; kh++) {
        int ih = h + kh - P;
        if (ih < 0 || ih >= HH) continue;
        float2 inv[IW];
        #pragma unroll
        for (int i = 0; i < IW; i++) {
            int iw = w0 - P + i;
            inv[i] = (iw >= 0 && iw < WW)
                   ? __bfloat1622float2(base[((size_t)ih * WW + iw) * 64])
                   : make_float2(0.0f, 0.0f);
        }
        #pragma unroll
        for (int kx = 0; kx < KS; kx++) {
            float2 wv = kw[kh * KS + kx];
            #pragma unroll
            for (int o = 0; o < TW; o++) {
                acc[o].x += inv[o + kx].x * wv.x;
                acc[o].y += inv[o + kx].y * wv.y;
            }
        }
    }
    size_t opix = (size_t)b * LL + (size_t)h * WW + w0;
    bf162* outp = (bf162*)out;
    bf162* cap  = (bf162*)ctxall;
    #pragma unroll
    for (int o = 0; o < TW; o++) {
        float vx = gelu_f(acc[o].x), vy = gelu_f(acc[o].y);
        outp[(opix + o) * 64 + cp] = __floats2bfloat162_rn(vx, vy);
        float gt = gates[(opix + o) * 4 + gidx];
        if (INIT) {
            cap[(opix + o) * 64 + cp] = __floats2bfloat162_rn(vx * gt, vy * gt);
        } else {
            float2 cur = __bfloat1622float2(cap[(opix + o) * 64 + cp]);
            cap[(opix + o) * 64 + cp] = __floats2bfloat162_rn(cur.x + vx * gt, cur.y + vy * gt);
        }
    }
}

// ---------------- global mean pool + gelu ----------------
__global__ void pool_kernel(const bf16* __restrict__ ctx, float* __restrict__ pool)
{
    __shared__ float sm[8][128];
    int b = blockIdx.x;
    int tid = threadIdx.x;
    int c = tid & 127, s = tid >> 7;
    const bf16* p = ctx + ((size_t)b * LL + (size_t)s * (LL / 8)) * CC + c;
    float acc = 0.0f;
    for (int i = 0; i < LL / 8; i++) acc += __bfloat162float(p[(size_t)i * CC]);
    sm[s][c] = acc;
    __syncthreads();
    if (s == 0) {
        float t = 0.0f;
        #pragma unroll
        for (int k = 0; k < 8; k++) t += sm[k][c];
        pool[b * CC + c] = gelu_f(t * (1.0f / LL));
    }
}

// ---------------- P2[b,n] = pool[b,:] @ h_w[:,n] ----------------
__global__ void p2_kernel(const float* __restrict__ pool,
                          const float* __restrict__ h_w,
                          float* __restrict__ P2)
{
    __shared__ float prow[128];
    int b = blockIdx.x, n = threadIdx.x;
    prow[n] = pool[b * CC + n];
    __syncthreads();
    float s = 0.0f;
    #pragma unroll 8
    for (int k = 0; k < CC; k++) s += prow[k] * h_w[k * CC + n];
    P2[b * CC + n] = s;
}

// ---------------- launch ----------------
extern "C" void kernel_launch(void* const* d_in, const int* in_sizes, int n_in,
                              void* d_out, int out_size)
{
    const float* x      = (const float*)d_in[0];
    const float* f_w    = (const float*)d_in[1];
    const float* f_b    = (const float*)d_in[2];
    const float* k0     = (const float*)d_in[3];
    const float* k1     = (const float*)d_in[4];
    const float* k2     = (const float*)d_in[5];
    const float* h_w    = (const float*)d_in[6];
    const float* h_b    = (const float*)d_in[7];
    const float* proj_w = (const float*)d_in[8];
    const float* proj_b = (const float*)d_in[9];
    const float* ln1_g  = (const float*)d_in[10];
    const float* ln1_b  = (const float*)d_in[11];
    const float* ln2_g  = (const float*)d_in[12];
    const float* ln2_b  = (const float*)d_in[13];
    const float* fc1_w  = (const float*)d_in[14];
    const float* fc1_b  = (const float*)d_in[15];
    const float* fc2_w  = (const float*)d_in[16];
    const float* fc2_b  = (const float*)d_in[17];
    float* out = (float*)d_out;

    bf16 *y, *q, *c0, *c1, *call, *y2, *c2, *hid, *wt;
    float *gts, *pl, *p2, *x1;
    cudaGetSymbolAddress((void**)&y,    g_y);
    cudaGetSymbolAddress((void**)&q,    g_q);
    cudaGetSymbolAddress((void**)&c0,   g_c0);
    cudaGetSymbolAddress((void**)&c1,   g_c1);
    cudaGetSymbolAddress((void**)&call, g_call);
    cudaGetSymbolAddress((void**)&y2,   g_y2);
    cudaGetSymbolAddress((void**)&c2,   g_c2);
    cudaGetSymbolAddress((void**)&hid,  g_hid);
    cudaGetSymbolAddress((void**)&gts,  g_gates);
    cudaGetSymbolAddress((void**)&pl,   g_pool);
    cudaGetSymbolAddress((void**)&p2,   g_p2);
    cudaGetSymbolAddress((void**)&x1,   g_x1);
    cudaGetSymbolAddress((void**)&wt,   g_wt);

    const int MBLK = MM / 128;                 // 1568
    dim3 g1(MBLK, 1), g2(MBLK, 2), g4(MBLK, 4);
    const int conv_grid = BB * HH * (WW / 8);  // 25088

    // 1. pack weights
    pack_all<<<768, 256>>>(f_w, h_w, proj_w, fc1_w, fc2_w, wt);
    // 2. y = LN1(x) + fused gates
    ln_kernel<true><<<3136, 256>>>(x, ln1_g, ln1_b, y, f_w, f_b, gts);
    // 3. fused q|ctx GEMM (N=256)
    bf_gemm<4><<<g2, 256>>>(y, CC, wt + WT_QC, f_b, q, CC, c0, CC, CC, nullptr, nullptr);
    // 4-6. focal levels
    dwconv_kernel<3, true ><<<conv_grid, 64>>>(c0, k0, gts, c1, call, 0);
    dwconv_kernel<5, false><<<conv_grid, 64>>>(c1, k1, gts, c0, call, 1);
    dwconv_kernel<7, false><<<conv_grid, 64>>>(c0, k2, gts, c1, call, 2);
    // 7. pool = gelu(mean(ctx3))
    pool_kernel<<<BB, 1024>>>(c1, pl);
    // 8. P2 = pool @ h_w
    p2_kernel<<<BB, 128>>>(pl, h_w, p2);
    // 9. y2 = (ctxall @ h_w + h_b + gate3*P2) * q
    bf_gemm<5><<<g1, 256>>>(call, CC, wt + WT_H, h_b, y2, CC, q, CC, CC, gts, p2);
    // 10. x1 = x + (y2 @ proj_w + proj_b)   (fp32)
    bf_gemm<3><<<g1, 256>>>(y2, CC, wt + WT_PROJ, proj_b, x1, CC, x, CC, CC, nullptr, nullptr);
    // 11. c2 = LN2(x1)
    ln_kernel<false><<<3136, 256>>>(x1, ln2_g, ln2_b, c2, nullptr, nullptr, nullptr);
    // 12. hid = gelu(c2 @ fc1_w + fc1_b)
    bf_gemm<1><<<g4, 256>>>(c2, CC, wt + WT_FC1, fc1_b, hid, HID, nullptr, 0, CC, nullptr, nullptr);
    // 13. out = x1 + (hid @ fc2_w + fc2_b)   (fp32)
    bf_gemm<3><<<g1, 256>>>(hid, HID, wt + WT_FC2, fc2_b, out, CC, x1, CC, HID, nullptr, nullptr);
}

// round 9
// speedup vs baseline: 1.1252x; 1.0433x over previous
#include <cuda_runtime.h>
#include <cuda_bf16.h>
#include <math.h>
#include <stdint.h>

// Problem constants (B=64, H=W=56, C=128)
#define BB 64
#define HH 56
#define WW 56
#define CC 128
#define LL (HH*WW)            // 3136
#define MM (BB*LL)            // 200704
#define HID 512
#define FWLD 260

typedef __nv_bfloat16 bf16;
typedef __nv_bfloat162 bf162;

// ---------------- scratch ----------------
__device__ bf16  g_y[(size_t)MM*CC];
__device__ bf16  g_q[(size_t)MM*CC];
__device__ bf16  g_c0[(size_t)MM*CC];
__device__ bf16  g_c1[(size_t)MM*CC];
__device__ bf16  g_call[(size_t)MM*CC];
__device__ bf16  g_y2[(size_t)MM*CC];
__device__ bf16  g_c2[(size_t)MM*CC];
__device__ bf16  g_hid[(size_t)MM*HID];
__device__ float g_gates[(size_t)MM*4];
__device__ float g_pool[BB*CC];
__device__ float g_p2[BB*CC];
__device__ float g_x1[(size_t)MM*CC];
__device__ bf16  g_wt[196608];             // packed bf16 weights, [N][K]

#define WT_QC   0        // [256,128]  (q then ctx)
#define WT_H    32768    // [128,128]
#define WT_PROJ 49152    // [128,128]
#define WT_FC1  65536    // [512,128]
#define WT_FC2  131072   // [128,512]

__device__ __forceinline__ float gelu_f(float x) {
    float y = 0.7978845608028654f * (x + 0.044715f * x * x * x);
    float t; asm("tanh.approx.f32 %0, %1;" : "=f"(t) : "f"(y));
    return 0.5f * x * (1.0f + t);
}
__device__ __forceinline__ uint32_t smem_u32(const void* p) {
    uint32_t a;
    asm("{ .reg .u64 t; cvta.to.shared.u64 t, %1; cvt.u32.u64 %0, t; }" : "=r"(a) : "l"(p));
    return a;
}
__device__ __forceinline__ void cp16(uint32_t dst, const void* src) {
    asm volatile("cp.async.cg.shared.global [%0], [%1], 16;" :: "r"(dst), "l"(src));
}
__device__ __forceinline__ void mma_bf16(float* d, const uint32_t* a, const uint32_t* b) {
    asm volatile(
        "mma.sync.aligned.m16n8k16.row.col.f32.bf16.bf16.f32 "
        "{%0,%1,%2,%3}, {%4,%5,%6,%7}, {%8,%9}, {%0,%1,%2,%3};"
        : "+f"(d[0]), "+f"(d[1]), "+f"(d[2]), "+f"(d[3])
        : "r"(a[0]), "r"(a[1]), "r"(a[2]), "r"(a[3]), "r"(b[0]), "r"(b[1]));
}
__device__ __forceinline__ void ldsm_x4(uint32_t* d, uint32_t addr) {
    asm volatile("ldmatrix.sync.aligned.m8n8.x4.shared.b16 {%0,%1,%2,%3}, [%4];"
        : "=r"(d[0]), "=r"(d[1]), "=r"(d[2]), "=r"(d[3]) : "r"(addr));
}

// ======== bf16 mma.sync GEMM: C[M,N] = epi(A[M,K] @ Bt[N,K]^T + bias) ========
// grid (M/128, N/128), 256 threads (8 warps 2x4), warp tile 64x32, BK=32.
// EPI: 0 none->bf16, 1 gelu->bf16, 2 *extra(bf16)->bf16, 3 +extra(f32)->f32,
//      4 dual bf16 out, 5 modulator (+g3*P2)*extra,
//      6 proj: +extra(f32)->Cp(f32)=x1, then LN2(x1)->c2out(bf16). Needs grid.y==1.
template<int EPI>
__global__ void __launch_bounds__(256, 2)
bf_gemm(const bf16* __restrict__ A, int lda,
        const bf16* __restrict__ Bt,
        const float* __restrict__ bias,
        void* __restrict__ Cp, int ldc,
        const void* __restrict__ extrap, int lde,
        int K,
        const float* __restrict__ g3,
        const float* __restrict__ P2v,
        const float* __restrict__ ln2g,
        const float* __restrict__ ln2b,
        bf16* __restrict__ c2out)
{
    __shared__ uint32_t As2[2][128][20];   // 32 halves = 16 words + 4 pad
    __shared__ uint32_t Bs2[2][128][20];

    const int tid  = threadIdx.x;
    const int lane = tid & 31, warp = tid >> 5;
    const int row  = lane >> 2, col = lane & 3;
    const int g8   = lane >> 3, r8 = lane & 7;   // ldmatrix groups
    const int wm   = (warp >> 2) * 64;
    const int wn   = (warp & 3) * 32;
    const int m0   = blockIdx.x * 128, n0 = blockIdx.y * 128;

    const uint32_t sA = smem_u32(As2), sB = smem_u32(Bs2);
    const bf16* Ab = A + (size_t)m0 * lda;
    const bf16* Bb = Bt + (size_t)n0 * K;

    float acc[4][4][4];
    #pragma unroll
    for (int i = 0; i < 4; i++)
        #pragma unroll
        for (int j = 0; j < 4; j++)
            #pragma unroll
            for (int r = 0; r < 4; r++) acc[i][j][r] = 0.0f;

    const int r_ld = tid >> 2, s_ld = tid & 3;   // 128 rows x 4 x 16B
    auto load_chunk = [&](int kc, int buf) {
        #pragma unroll
        for (int t = 0; t < 2; t++) {
            int r = r_ld + t * 64;
            cp16(sA + (uint32_t)((((buf * 128 + r) * 20) + s_ld * 4) * 4),
                 Ab + (size_t)r * lda + kc + s_ld * 8);
        }
        #pragma unroll
        for (int t = 0; t < 2; t++) {
            int r = r_ld + t * 64;
            cp16(sB + (uint32_t)((((buf * 128 + r) * 20) + s_ld * 4) * 4),
                 Bb + (size_t)r * K + kc + s_ld * 8);
        }
        asm volatile("cp.async.commit_group;" ::: "memory");
    };

    const int NC = K / 32;
    load_chunk(0, 0);

    for (int i = 0; i < NC; i++) {
        int b = i & 1;
        if (i + 1 < NC) {
            load_chunk((i + 1) * 32, b ^ 1);
            asm volatile("cp.async.wait_group 1;" ::: "memory");
        } else {
            asm volatile("cp.async.wait_group 0;" ::: "memory");
        }
        __syncthreads();

        #pragma unroll
        for (int kk = 0; kk < 2; kk++) {
            const int wo = kk * 8;
            uint32_t af[4][4], bq[2][4];
            #pragma unroll
            for (int mt = 0; mt < 4; mt++) {
                int ar = wm + mt * 16 + (g8 & 1) * 8 + r8;
                uint32_t addr = sA + (uint32_t)((((b * 128 + ar) * 20) + wo + (g8 >> 1) * 4) * 4);
                ldsm_x4(af[mt], addr);
            }
            #pragma unroll
            for (int p = 0; p < 2; p++) {
                int br = wn + p * 16 + (g8 >> 1) * 8 + r8;
                uint32_t addr = sB + (uint32_t)((((b * 128 + br) * 20) + wo + (g8 & 1) * 4) * 4);
                ldsm_x4(bq[p], addr);
            }
            #pragma unroll
            for (int mt = 0; mt < 4; mt++)
                #pragma unroll
                for (int nt = 0; nt < 4; nt++)
                    mma_bf16(acc[mt][nt], af[mt], &bq[nt >> 1][(nt & 1) * 2]);
        }
        __syncthreads();
    }

    // -------- epilogue --------
    bf16*  Cb = (bf16*)Cp;
    float* Cf = (float*)Cp;
    const bf16*  Eb = (const bf16*)extrap;
    const float* Ef = (const float*)extrap;

    if (EPI == 6) {
        // x1 = acc + bias + x (fp32 out), then LN2 over the full row -> c2out bf16
        float psum[4][2], psq[4][2];
        #pragma unroll
        for (int mt = 0; mt < 4; mt++)
            #pragma unroll
            for (int h2 = 0; h2 < 2; h2++) { psum[mt][h2] = 0.0f; psq[mt][h2] = 0.0f; }

        #pragma unroll
        for (int mt = 0; mt < 4; mt++) {
            #pragma unroll
            for (int nt = 0; nt < 4; nt++) {
                int m = m0 + wm + mt * 16 + row;
                int n = wn + nt * 8 + 2 * col;
                float2 bv = *(const float2*)(bias + n);
                #pragma unroll
                for (int h2 = 0; h2 < 2; h2++) {
                    int mg = m + h2 * 8;
                    float vx = acc[mt][nt][h2 * 2 + 0] + bv.x;
                    float vy = acc[mt][nt][h2 * 2 + 1] + bv.y;
                    float2 e = *(const float2*)(Ef + (size_t)mg * lde + n);
                    vx += e.x; vy += e.y;
                    *(float2*)(Cf + (size_t)mg * ldc + n) = make_float2(vx, vy);
                    acc[mt][nt][h2 * 2 + 0] = vx;
                    acc[mt][nt][h2 * 2 + 1] = vy;
                    psum[mt][h2] += vx + vy;
                    psq[mt][h2]  += vx * vx + vy * vy;
                }
            }
        }
        // reduce over the 4 col lanes (same row)
        #pragma unroll
        for (int mt = 0; mt < 4; mt++)
            #pragma unroll
            for (int h2 = 0; h2 < 2; h2++) {
                #pragma unroll
                for (int o = 1; o <= 2; o <<= 1) {
                    psum[mt][h2] += __shfl_xor_sync(0xffffffffu, psum[mt][h2], o);
                    psq[mt][h2]  += __shfl_xor_sync(0xffffffffu, psq[mt][h2], o);
                }
            }
        float2* red = (float2*)As2;    // [128 rows][4 warps], reuse dead smem
        int wg = warp & 3;
        if (col == 0) {
            #pragma unroll
            for (int mt = 0; mt < 4; mt++)
                #pragma unroll
                for (int h2 = 0; h2 < 2; h2++) {
                    int lr = wm + mt * 16 + h2 * 8 + row;
                    red[lr * 4 + wg] = make_float2(psum[mt][h2], psq[mt][h2]);
                }
        }
        __syncthreads();
        #pragma unroll
        for (int mt = 0; mt < 4; mt++) {
            #pragma unroll
            for (int h2 = 0; h2 < 2; h2++) {
                int lr = wm + mt * 16 + h2 * 8 + row;
                float s = 0.0f, qq = 0.0f;
                #pragma unroll
                for (int w2 = 0; w2 < 4; w2++) {
                    float2 p = red[lr * 4 + w2];
                    s += p.x; qq += p.y;
                }
                float mu = s * (1.0f / 128.0f);
                float var = qq * (1.0f / 128.0f) - mu * mu;
                float rr = rsqrtf(var + 1e-5f);
                int mg = m0 + lr;
                #pragma unroll
                for (int nt = 0; nt < 4; nt++) {
                    int n = wn + nt * 8 + 2 * col;
                    float2 gv = *(const float2*)(ln2g + n);
                    float2 bv2 = *(const float2*)(ln2b + n);
                    float ox = (acc[mt][nt][h2 * 2 + 0] - mu) * rr * gv.x + bv2.x;
                    float oy = (acc[mt][nt][h2 * 2 + 1] - mu) * rr * gv.y + bv2.y;
                    *(bf162*)(c2out + (size_t)mg * CC + n) = __floats2bfloat162_rn(ox, oy);
                }
            }
        }
        return;
    }

    #pragma unroll
    for (int mt = 0; mt < 4; mt++) {
        #pragma unroll
        for (int nt = 0; nt < 4; nt++) {
            int m = m0 + wm + mt * 16 + row;
            int n = n0 + wn + nt * 8 + 2 * col;
            float2 bv = *(const float2*)(bias + n);
            #pragma unroll
            for (int half = 0; half < 2; half++) {
                int mg = m + half * 8;
                float2 o;
                o.x = acc[mt][nt][half * 2 + 0] + bv.x;
                o.y = acc[mt][nt][half * 2 + 1] + bv.y;
                if (EPI == 0) {
                    *(bf162*)(Cb + (size_t)mg * ldc + n) = __floats2bfloat162_rn(o.x, o.y);
                } else if (EPI == 1) {
                    o.x = gelu_f(o.x); o.y = gelu_f(o.y);
                    *(bf162*)(Cb + (size_t)mg * ldc + n) = __floats2bfloat162_rn(o.x, o.y);
                } else if (EPI == 2) {
                    float2 e = __bfloat1622float2(*(const bf162*)(Eb + (size_t)mg * lde + n));
                    o.x *= e.x; o.y *= e.y;
                    *(bf162*)(Cb + (size_t)mg * ldc + n) = __floats2bfloat162_rn(o.x, o.y);
                } else if (EPI == 3) {
                    float2 e = *(const float2*)(Ef + (size_t)mg * lde + n);
                    o.x += e.x; o.y += e.y;
                    *(float2*)(Cf + (size_t)mg * ldc + n) = o;
                } else if (EPI == 4) {
                    bf16* dst = (n0 == 0) ? Cb : (bf16*)const_cast<void*>(extrap);
                    int nl = n - n0;
                    *(bf162*)(dst + (size_t)mg * ldc + nl) = __floats2bfloat162_rn(o.x, o.y);
                } else {  // EPI == 5
                    int bidx = mg / LL;
                    float gate = g3[(size_t)mg * 4 + 3];
                    float2 p2 = *(const float2*)(P2v + bidx * CC + n);
                    o.x += gate * p2.x; o.y += gate * p2.y;
                    float2 e = __bfloat1622float2(*(const bf162*)(Eb + (size_t)mg * lde + n));
                    o.x *= e.x; o.y *= e.y;
                    *(bf162*)(Cb + (size_t)mg * ldc + n) = __floats2bfloat162_rn(o.x, o.y);
                }
            }
        }
    }
}

// ------------- fused weight pack (transpose) to bf16 [N][K] -------------
__global__ void pack_all(const float* __restrict__ f_w, const float* __restrict__ h_w,
                         const float* __restrict__ proj_w, const float* __restrict__ fc1_w,
                         const float* __restrict__ fc2_w, bf16* __restrict__ wt)
{
    int idx = blockIdx.x * 256 + threadIdx.x;
    if (idx >= 196608) return;
    float v;
    if (idx < 32768) {
        int n = idx >> 7, k = idx & 127;
        v = f_w[k * FWLD + n];
    } else if (idx < 49152) {
        int j = idx - 32768; int n = j >> 7, k = j & 127;
        v = h_w[k * 128 + n];
    } else if (idx < 65536) {
        int j = idx - 49152; int n = j >> 7, k = j & 127;
        v = proj_w[k * 128 + n];
    } else if (idx < 131072) {
        int j = idx - 65536; int n = j >> 7, k = j & 127;
        v = fc1_w[k * 512 + n];
    } else {
        int j = idx - 131072; int n = j / 512, k = j % 512;
        v = fc2_w[k * 128 + n];
    }
    wt[idx] = __float2bfloat16(v);
}

// ---------------- LayerNorm (+fused gates GEMV), grid-stride ----------------
template<bool GATES>
__global__ void ln_kernel(const float* __restrict__ x,
                          const float* __restrict__ g,
                          const float* __restrict__ b,
                          bf16* __restrict__ y,
                          const float* __restrict__ fw,
                          const float* __restrict__ fb,
                          float* __restrict__ gates)
{
    const int lane = threadIdx.x & 31;
    const int gwarp = (blockIdx.x * blockDim.x + threadIdx.x) >> 5;
    const int nwarp = (gridDim.x * blockDim.x) >> 5;

    float4 gg = ((const float4*)g)[lane];
    float4 bb = ((const float4*)b)[lane];
    float w[4][4], fbs[4];
    if (GATES) {
        int k0 = lane * 4;
        #pragma unroll
        for (int c = 0; c < 4; c++)
            #pragma unroll
            for (int j = 0; j < 4; j++)
                w[c][j] = fw[(k0 + c) * FWLD + 256 + j];
        #pragma unroll
        for (int j = 0; j < 4; j++) fbs[j] = fb[256 + j];
    }

    for (int tok = gwarp; tok < MM; tok += nwarp) {
        float4 v = ((const float4*)(x + (size_t)tok * CC))[lane];
        float s = v.x + v.y + v.z + v.w;
        #pragma unroll
        for (int o = 16; o; o >>= 1) s += __shfl_xor_sync(0xffffffffu, s, o);
        float mu = s * (1.0f / CC);
        float dx = v.x - mu, dy = v.y - mu, dz = v.z - mu, dw = v.w - mu;
        float s2 = dx*dx + dy*dy + dz*dz + dw*dw;
        #pragma unroll
        for (int o = 16; o; o >>= 1) s2 += __shfl_xor_sync(0xffffffffu, s2, o);
        float r = rsqrtf(s2 * (1.0f / CC) + 1e-5f);
        float y0 = dx * r * gg.x + bb.x;
        float y1 = dy * r * gg.y + bb.y;
        float y2v = dz * r * gg.z + bb.z;
        float y3 = dw * r * gg.w + bb.w;
        bf162 p0 = __floats2bfloat162_rn(y0, y1);
        bf162 p1 = __floats2bfloat162_rn(y2v, y3);
        uint2 u;
        u.x = *(uint32_t*)&p0; u.y = *(uint32_t*)&p1;
        ((uint2*)(y + (size_t)tok * CC))[lane] = u;

        if (GATES) {
            float sg[4];
            #pragma unroll
            for (int j = 0; j < 4; j++) {
                sg[j] = y0 * w[0][j] + y1 * w[1][j] + y2v * w[2][j] + y3 * w[3][j];
                #pragma unroll
                for (int o = 16; o; o >>= 1) sg[j] += __shfl_xor_sync(0xffffffffu, sg[j], o);
            }
            if (lane == 0) {
                float4 gv = make_float4(sg[0] + fbs[0], sg[1] + fbs[1],
                                        sg[2] + fbs[2], sg[3] + fbs[3]);
                *(float4*)(gates + (size_t)tok * 4) = gv;
            }
        }
    }
}

// ---------------- depthwise conv (channel-pair vectorized, TW=8) ----------------
// MODE 0: conv3 — write out only.
// MODE 1: conv5 — write out, and call = g0*center + g1*v  (write-only).
// MODE 2: conv7 — write out, and call += g2*v (RMW).
template<int KS, int MODE>
__global__ void dwconv_kernel(const bf16* __restrict__ in,
                              const float* __restrict__ kern,
                              const float* __restrict__ gates,
                              bf16* __restrict__ out,
                              bf16* __restrict__ ctxall)
{
    constexpr int P = KS / 2, TW = 8, IW = TW + KS - 1;
    int cp = threadIdx.x;                     // channel pair 0..63
    int blk = blockIdx.x;                     // B*H*(W/TW)
    int wt = blk % (WW / TW);
    int rem = blk / (WW / TW);
    int h = rem % HH;
    int b = rem / HH;
    int w0 = wt * TW;

    float2 kw[KS * KS];
    #pragma unroll
    for (int i = 0; i < KS * KS; i++)
        kw[i] = make_float2(kern[i * CC + 2 * cp], kern[i * CC + 2 * cp + 1]);

    float2 acc[TW];
    #pragma unroll
    for (int o = 0; o < TW; o++) acc[o] = make_float2(0.0f, 0.0f);
    float2 center[TW];

    const bf162* base = (const bf162*)in + (size_t)b * LL * 64 + cp;
    #pragma unroll
    for (int kh = 0; kh < KS; kh++) {
        int ih = h + kh - P;
        if (ih < 0 || ih >= HH) continue;
        float2 inv[IW];
        #pragma unroll
        for (int i = 0; i < IW; i++) {
            int iw = w0 - P + i;
            inv[i] = (iw >= 0 && iw < WW)
                   ? __bfloat1622float2(base[((size_t)ih * WW + iw) * 64])
                   : make_float2(0.0f, 0.0f);
        }
        if (MODE == 1 && kh == P) {
            #pragma unroll
            for (int o = 0; o < TW; o++) center[o] = inv[o + P];
        }
        #pragma unroll
        for (int kx = 0; kx < KS; kx++) {
            float2 wv = kw[kh * KS + kx];
            #pragma unroll
            for (int o = 0; o < TW; o++) {
                acc[o].x += inv[o + kx].x * wv.x;
                acc[o].y += inv[o + kx].y * wv.y;
            }
        }
    }
    size_t opix = (size_t)b * LL + (size_t)h * WW + w0;
    bf162* outp = (bf162*)out;
    bf162* cap  = (bf162*)ctxall;
    #pragma unroll
    for (int o = 0; o < TW; o++) {
        float vx = gelu_f(acc[o].x), vy = gelu_f(acc[o].y);
        outp[(opix + o) * 64 + cp] = __floats2bfloat162_rn(vx, vy);
        if (MODE == 1) {
            float g0 = gates[(opix + o) * 4 + 0];
            float g1 = gates[(opix + o) * 4 + 1];
            cap[(opix + o) * 64 + cp] = __floats2bfloat162_rn(
                center[o].x * g0 + vx * g1, center[o].y * g0 + vy * g1);
        } else if (MODE == 2) {
            float g2 = gates[(opix + o) * 4 + 2];
            float2 cur = __bfloat1622float2(cap[(opix + o) * 64 + cp]);
            cap[(opix + o) * 64 + cp] = __floats2bfloat162_rn(
                cur.x + vx * g2, cur.y + vy * g2);
        }
    }
}

// ---------------- global mean pool + gelu ----------------
__global__ void pool_kernel(const bf16* __restrict__ ctx, float* __restrict__ pool)
{
    __shared__ float sm[8][128];
    int b = blockIdx.x;
    int tid = threadIdx.x;
    int c = tid & 127, s = tid >> 7;
    const bf16* p = ctx + ((size_t)b * LL + (size_t)s * (LL / 8)) * CC + c;
    float acc = 0.0f;
    for (int i = 0; i < LL / 8; i++) acc += __bfloat162float(p[(size_t)i * CC]);
    sm[s][c] = acc;
    __syncthreads();
    if (s == 0) {
        float t = 0.0f;
        #pragma unroll
        for (int k = 0; k < 8; k++) t += sm[k][c];
        pool[b * CC + c] = gelu_f(t * (1.0f / LL));
    }
}

// ---------------- P2[b,n] = pool[b,:] @ h_w[:,n] ----------------
__global__ void p2_kernel(const float* __restrict__ pool,
                          const float* __restrict__ h_w,
                          float* __restrict__ P2)
{
    __shared__ float prow[128];
    int b = blockIdx.x, n = threadIdx.x;
    prow[n] = pool[b * CC + n];
    __syncthreads();
    float s = 0.0f;
    #pragma unroll 8
    for (int k = 0; k < CC; k++) s += prow[k] * h_w[k * CC + n];
    P2[b * CC + n] = s;
}

// ---------------- launch ----------------
extern "C" void kernel_launch(void* const* d_in, const int* in_sizes, int n_in,
                              void* d_out, int out_size)
{
    const float* x      = (const float*)d_in[0];
    const float* f_w    = (const float*)d_in[1];
    const float* f_b    = (const float*)d_in[2];
    const float* k0     = (const float*)d_in[3];
    const float* k1     = (const float*)d_in[4];
    const float* k2     = (const float*)d_in[5];
    const float* h_w    = (const float*)d_in[6];
    const float* h_b    = (const float*)d_in[7];
    const float* proj_w = (const float*)d_in[8];
    const float* proj_b = (const float*)d_in[9];
    const float* ln1_g  = (const float*)d_in[10];
    const float* ln1_b  = (const float*)d_in[11];
    const float* ln2_g  = (const float*)d_in[12];
    const float* ln2_b  = (const float*)d_in[13];
    const float* fc1_w  = (const float*)d_in[14];
    const float* fc1_b  = (const float*)d_in[15];
    const float* fc2_w  = (const float*)d_in[16];
    const float* fc2_b  = (const float*)d_in[17];
    float* out = (float*)d_out;

    bf16 *y, *q, *c0, *c1, *call, *y2, *c2, *hid, *wt;
    float *gts, *pl, *p2, *x1;
    cudaGetSymbolAddress((void**)&y,    g_y);
    cudaGetSymbolAddress((void**)&q,    g_q);
    cudaGetSymbolAddress((void**)&c0,   g_c0);
    cudaGetSymbolAddress((void**)&c1,   g_c1);
    cudaGetSymbolAddress((void**)&call, g_call);
    cudaGetSymbolAddress((void**)&y2,   g_y2);
    cudaGetSymbolAddress((void**)&c2,   g_c2);
    cudaGetSymbolAddress((void**)&hid,  g_hid);
    cudaGetSymbolAddress((void**)&gts,  g_gates);
    cudaGetSymbolAddress((void**)&pl,   g_pool);
    cudaGetSymbolAddress((void**)&p2,   g_p2);
    cudaGetSymbolAddress((void**)&x1,   g_x1);
    cudaGetSymbolAddress((void**)&wt,   g_wt);

    const int MBLK = MM / 128;                 // 1568
    dim3 g1(MBLK, 1), g2(MBLK, 2), g4(MBLK, 4);
    const int conv_grid = BB * HH * (WW / 8);  // 25088

    // 1. pack weights
    pack_all<<<768, 256>>>(f_w, h_w, proj_w, fc1_w, fc2_w, wt);
    // 2. y = LN1(x) + fused gates
    ln_kernel<true><<<3136, 256>>>(x, ln1_g, ln1_b, y, f_w, f_b, gts);
    // 3. fused q|ctx GEMM (N=256)
    bf_gemm<4><<<g2, 256>>>(y, CC, wt + WT_QC, f_b, q, CC, c0, CC, CC,
                            nullptr, nullptr, nullptr, nullptr, nullptr);
    // 4-6. focal levels (ctxall chain fused into conv5/conv7)
    dwconv_kernel<3, 0><<<conv_grid, 64>>>(c0, k0, gts, c1, call);
    dwconv_kernel<5, 1><<<conv_grid, 64>>>(c1, k1, gts, c0, call);
    dwconv_kernel<7, 2><<<conv_grid, 64>>>(c0, k2, gts, c1, call);
    // 7. pool = gelu(mean(ctx3))
    pool_kernel<<<BB, 1024>>>(c1, pl);
    // 8. P2 = pool @ h_w
    p2_kernel<<<BB, 128>>>(pl, h_w, p2);
    // 9. y2 = (ctxall @ h_w + h_b + gate3*P2) * q
    bf_gemm<5><<<g1, 256>>>(call, CC, wt + WT_H, h_b, y2, CC, q, CC, CC,
                            gts, p2, nullptr, nullptr, nullptr);
    // 10. x1 = x + (y2 @ proj_w + proj_b), fused LN2 -> c2
    bf_gemm<6><<<g1, 256>>>(y2, CC, wt + WT_PROJ, proj_b, x1, CC, x, CC, CC,
                            nullptr, nullptr, ln2_g, ln2_b, c2);
    // 11. hid = gelu(c2 @ fc1_w + fc1_b)
    bf_gemm<1><<<g4, 256>>>(c2, CC, wt + WT_FC1, fc1_b, hid, HID, nullptr, 0, CC,
                            nullptr, nullptr, nullptr, nullptr, nullptr);
    // 12. out = x1 + (hid @ fc2_w + fc2_b)   (fp32)
    bf_gemm<3><<<g1, 256>>>(hid, HID, wt + WT_FC2, fc2_b, out, CC, x1, CC, HID,
                            nullptr, nullptr, nullptr, nullptr, nullptr);
}

// round 10
// speedup vs baseline: 1.1542x; 1.0257x over previous
#include <cuda_runtime.h>
#include <cuda_bf16.h>
#include <math.h>
#include <stdint.h>

// Problem constants (B=64, H=W=56, C=128)
#define BB 64
#define HH 56
#define WW 56
#define CC 128
#define LL (HH*WW)            // 3136
#define MM (BB*LL)            // 200704
#define HID 512
#define FWLD 260

typedef __nv_bfloat16 bf16;
typedef __nv_bfloat162 bf162;

// ---------------- scratch ----------------
__device__ bf16  g_y[(size_t)MM*CC];
__device__ bf16  g_q[(size_t)MM*CC];
__device__ bf16  g_c0[(size_t)MM*CC];
__device__ bf16  g_c1[(size_t)MM*CC];
__device__ bf16  g_call[(size_t)MM*CC];
__device__ bf16  g_c2[(size_t)MM*CC];
__device__ float g_gates[(size_t)MM*4];
__device__ float g_pool[BB*CC];
__device__ float g_p2[BB*CC];
__device__ float g_x1[(size_t)MM*CC];
__device__ bf16  g_wt[196608];             // packed bf16 weights, [N][K]

#define WT_QC   0        // [256,128]  (q then ctx)
#define WT_H    32768    // [128,128]
#define WT_PROJ 49152    // [128,128]
#define WT_FC1  65536    // [512,128]
#define WT_FC2  131072   // [128,512]

__device__ __forceinline__ float gelu_f(float x) {
    float y = 0.7978845608028654f * (x + 0.044715f * x * x * x);
    float t; asm("tanh.approx.f32 %0, %1;" : "=f"(t) : "f"(y));
    return 0.5f * x * (1.0f + t);
}
__device__ __forceinline__ uint32_t smem_u32(const void* p) {
    uint32_t a;
    asm("{ .reg .u64 t; cvta.to.shared.u64 t, %1; cvt.u32.u64 %0, t; }" : "=r"(a) : "l"(p));
    return a;
}
__device__ __forceinline__ void cp16(uint32_t dst, const void* src) {
    asm volatile("cp.async.cg.shared.global [%0], [%1], 16;" :: "r"(dst), "l"(src));
}
__device__ __forceinline__ void mma_bf16(float* d, const uint32_t* a, const uint32_t* b) {
    asm volatile(
        "mma.sync.aligned.m16n8k16.row.col.f32.bf16.bf16.f32 "
        "{%0,%1,%2,%3}, {%4,%5,%6,%7}, {%8,%9}, {%0,%1,%2,%3};"
        : "+f"(d[0]), "+f"(d[1]), "+f"(d[2]), "+f"(d[3])
        : "r"(a[0]), "r"(a[1]), "r"(a[2]), "r"(a[3]), "r"(b[0]), "r"(b[1]));
}
__device__ __forceinline__ void ldsm_x4(uint32_t* d, uint32_t addr) {
    asm volatile("ldmatrix.sync.aligned.m8n8.x4.shared.b16 {%0,%1,%2,%3}, [%4];"
        : "=r"(d[0]), "=r"(d[1]), "=r"(d[2]), "=r"(d[3]) : "r"(addr));
}

// ======== bf16 mma.sync GEMM (q|ctx dual-output only, EPI4 pattern) ========
__global__ void __launch_bounds__(256, 2)
bf_gemm_qc(const bf16* __restrict__ A,
           const bf16* __restrict__ Bt,
           const float* __restrict__ bias,
           bf16* __restrict__ qout,
           bf16* __restrict__ ctxout)
{
    __shared__ uint32_t As2[2][128][20];
    __shared__ uint32_t Bs2[2][128][20];

    const int tid  = threadIdx.x;
    const int lane = tid & 31, warp = tid >> 5;
    const int row  = lane >> 2, col = lane & 3;
    const int g8   = lane >> 3, r8 = lane & 7;
    const int wm   = (warp >> 2) * 64;
    const int wn   = (warp & 3) * 32;
    const int m0   = blockIdx.x * 128, n0 = blockIdx.y * 128;

    const uint32_t sA = smem_u32(As2), sB = smem_u32(Bs2);
    const bf16* Ab = A + (size_t)m0 * CC;
    const bf16* Bb = Bt + (size_t)n0 * CC;

    float acc[4][4][4];
    #pragma unroll
    for (int i = 0; i < 4; i++)
        #pragma unroll
        for (int j = 0; j < 4; j++)
            #pragma unroll
            for (int r = 0; r < 4; r++) acc[i][j][r] = 0.0f;

    const int r_ld = tid >> 2, s_ld = tid & 3;
    auto load_chunk = [&](int kc, int buf) {
        #pragma unroll
        for (int t = 0; t < 2; t++) {
            int r = r_ld + t * 64;
            cp16(sA + (uint32_t)((((buf * 128 + r) * 20) + s_ld * 4) * 4),
                 Ab + (size_t)r * CC + kc + s_ld * 8);
            cp16(sB + (uint32_t)((((buf * 128 + r) * 20) + s_ld * 4) * 4),
                 Bb + (size_t)r * CC + kc + s_ld * 8);
        }
        asm volatile("cp.async.commit_group;" ::: "memory");
    };

    load_chunk(0, 0);
    for (int i = 0; i < 4; i++) {
        int b = i & 1;
        if (i + 1 < 4) {
            load_chunk((i + 1) * 32, b ^ 1);
            asm volatile("cp.async.wait_group 1;" ::: "memory");
        } else {
            asm volatile("cp.async.wait_group 0;" ::: "memory");
        }
        __syncthreads();
        #pragma unroll
        for (int kk = 0; kk < 2; kk++) {
            const int wo = kk * 8;
            uint32_t af[4][4], bq[2][4];
            #pragma unroll
            for (int mt = 0; mt < 4; mt++) {
                int ar = wm + mt * 16 + (g8 & 1) * 8 + r8;
                ldsm_x4(af[mt], sA + (uint32_t)((((b * 128 + ar) * 20) + wo + (g8 >> 1) * 4) * 4));
            }
            #pragma unroll
            for (int p = 0; p < 2; p++) {
                int br = wn + p * 16 + (g8 >> 1) * 8 + r8;
                ldsm_x4(bq[p], sB + (uint32_t)((((b * 128 + br) * 20) + wo + (g8 & 1) * 4) * 4));
            }
            #pragma unroll
            for (int mt = 0; mt < 4; mt++)
                #pragma unroll
                for (int nt = 0; nt < 4; nt++)
                    mma_bf16(acc[mt][nt], af[mt], &bq[nt >> 1][(nt & 1) * 2]);
        }
        __syncthreads();
    }

    bf16* dst = (n0 == 0) ? qout : ctxout;
    #pragma unroll
    for (int mt = 0; mt < 4; mt++) {
        #pragma unroll
        for (int nt = 0; nt < 4; nt++) {
            int m = m0 + wm + mt * 16 + row;
            int n = wn + nt * 8 + 2 * col;
            float2 bv = *(const float2*)(bias + n0 + n);
            #pragma unroll
            for (int half = 0; half < 2; half++) {
                int mg = m + half * 8;
                float ox = acc[mt][nt][half * 2 + 0] + bv.x;
                float oy = acc[mt][nt][half * 2 + 1] + bv.y;
                *(bf162*)(dst + (size_t)mg * CC + n) = __floats2bfloat162_rn(ox, oy);
            }
        }
    }
}

// ======== fused H-gemm (modulator) + proj-gemm + residual + LN2 ========
// stage1: y2 = (call @ Ht + h_b + g3*P2) * q   -> smem (128x128 bf16, stride 68w)
// stage2: x1 = x + y2 @ projT + proj_b (fp32);  c2 = LN2(x1) (bf16)
__global__ void __launch_bounds__(256, 2)
hp_fused(const bf16* __restrict__ Acall,
         const bf16* __restrict__ Ht,
         const bf16* __restrict__ projt,
         const float* __restrict__ h_b,
         const bf16* __restrict__ q,
         const float* __restrict__ g3,
         const float* __restrict__ P2v,
         const float* __restrict__ x,
         const float* __restrict__ proj_b,
         float* __restrict__ x1,
         const float* __restrict__ ln2g,
         const float* __restrict__ ln2b,
         bf16* __restrict__ c2out)
{
    __shared__ uint32_t sm[11264];   // 44 KB

    const int tid  = threadIdx.x;
    const int lane = tid & 31, warp = tid >> 5;
    const int row  = lane >> 2, col = lane & 3;
    const int g8   = lane >> 3, r8 = lane & 7;
    const int wm   = (warp >> 2) * 64;
    const int wn   = (warp & 3) * 32;
    const int m0   = blockIdx.x * 128;

    const uint32_t sA  = smem_u32(sm);
    const uint32_t sB  = sA + 5120 * 4;
    const uint32_t sY  = sA;                 // y2: 128 x 68 words
    const uint32_t sB2 = sA + 8704 * 4;      // stage2 B: 128 x 20 words

    const bf16* Ab = Acall + (size_t)m0 * CC;

    float acc[4][4][4];
    #pragma unroll
    for (int i = 0; i < 4; i++)
        #pragma unroll
        for (int j = 0; j < 4; j++)
            #pragma unroll
            for (int r = 0; r < 4; r++) acc[i][j][r] = 0.0f;

    const int r_ld = tid >> 2, s_ld = tid & 3;
    auto load1 = [&](int kc, int buf) {
        #pragma unroll
        for (int t = 0; t < 2; t++) {
            int r = r_ld + t * 64;
            cp16(sA + (uint32_t)((((buf * 128 + r) * 20) + s_ld * 4) * 4),
                 Ab + (size_t)r * CC + kc + s_ld * 8);
            cp16(sB + (uint32_t)((((buf * 128 + r) * 20) + s_ld * 4) * 4),
                 Ht + (size_t)r * CC + kc + s_ld * 8);
        }
        asm volatile("cp.async.commit_group;" ::: "memory");
    };

    // ---- stage 1 mainloop (K=128) ----
    load1(0, 0);
    for (int i = 0; i < 4; i++) {
        int b = i & 1;
        if (i + 1 < 4) {
            load1((i + 1) * 32, b ^ 1);
            asm volatile("cp.async.wait_group 1;" ::: "memory");
        } else {
            asm volatile("cp.async.wait_group 0;" ::: "memory");
        }
        __syncthreads();
        #pragma unroll
        for (int kk = 0; kk < 2; kk++) {
            const int wo = kk * 8;
            uint32_t af[4][4], bq[2][4];
            #pragma unroll
            for (int mt = 0; mt < 4; mt++) {
                int ar = wm + mt * 16 + (g8 & 1) * 8 + r8;
                ldsm_x4(af[mt], sA + (uint32_t)((((b * 128 + ar) * 20) + wo + (g8 >> 1) * 4) * 4));
            }
            #pragma unroll
            for (int p = 0; p < 2; p++) {
                int br = wn + p * 16 + (g8 >> 1) * 8 + r8;
                ldsm_x4(bq[p], sB + (uint32_t)((((b * 128 + br) * 20) + wo + (g8 & 1) * 4) * 4));
            }
            #pragma unroll
            for (int mt = 0; mt < 4; mt++)
                #pragma unroll
                for (int nt = 0; nt < 4; nt++)
                    mma_bf16(acc[mt][nt], af[mt], &bq[nt >> 1][(nt & 1) * 2]);
        }
        __syncthreads();
    }

    // ---- epilogue 1: modulator -> y2 smem ----
    #pragma unroll
    for (int mt = 0; mt < 4; mt++) {
        #pragma unroll
        for (int nt = 0; nt < 4; nt++) {
            int ml = wm + mt * 16 + row;
            int n = wn + nt * 8 + 2 * col;
            float2 hb = *(const float2*)(h_b + n);
            #pragma unroll
            for (int h2 = 0; h2 < 2; h2++) {
                int mgl = ml + h2 * 8;
                int mg = m0 + mgl;
                float ox = acc[mt][nt][h2 * 2 + 0] + hb.x;
                float oy = acc[mt][nt][h2 * 2 + 1] + hb.y;
                int bidx = mg / LL;
                float gate = g3[(size_t)mg * 4 + 3];
                float2 p2 = *(const float2*)(P2v + bidx * CC + n);
                ox += gate * p2.x; oy += gate * p2.y;
                float2 e = __bfloat1622float2(*(const bf162*)(q + (size_t)mg * CC + n));
                ox *= e.x; oy *= e.y;
                bf162 pv = __floats2bfloat162_rn(ox, oy);
                sm[mgl * 68 + (n >> 1)] = *(uint32_t*)&pv;
            }
        }
    }
    __syncthreads();

    // ---- stage 2: y2 @ projT (K=128), B single-buffered ----
    #pragma unroll
    for (int i = 0; i < 4; i++)
        #pragma unroll
        for (int j = 0; j < 4; j++)
            #pragma unroll
            for (int r = 0; r < 4; r++) acc[i][j][r] = 0.0f;

    for (int c = 0; c < 4; c++) {
        __syncthreads();
        #pragma unroll
        for (int t = 0; t < 2; t++) {
            int r = r_ld + t * 64;
            cp16(sB2 + (uint32_t)(((r * 20) + s_ld * 4) * 4),
                 projt + (size_t)r * CC + c * 32 + s_ld * 8);
        }
        asm volatile("cp.async.commit_group;" ::: "memory");
        asm volatile("cp.async.wait_group 0;" ::: "memory");
        __syncthreads();
        #pragma unroll
        for (int kk = 0; kk < 2; kk++) {
            int s = c * 2 + kk;
            uint32_t af[4][4], bq[2][4];
            #pragma unroll
            for (int mt = 0; mt < 4; mt++) {
                int ar = wm + mt * 16 + (g8 & 1) * 8 + r8;
                ldsm_x4(af[mt], sY + (uint32_t)(((ar * 68) + 8 * s + (g8 >> 1) * 4) * 4));
            }
            #pragma unroll
            for (int p = 0; p < 2; p++) {
                int br = wn + p * 16 + (g8 >> 1) * 8 + r8;
                ldsm_x4(bq[p], sB2 + (uint32_t)(((br * 20) + kk * 8 + (g8 & 1) * 4) * 4));
            }
            #pragma unroll
            for (int mt = 0; mt < 4; mt++)
                #pragma unroll
                for (int nt = 0; nt < 4; nt++)
                    mma_bf16(acc[mt][nt], af[mt], &bq[nt >> 1][(nt & 1) * 2]);
        }
    }
    __syncthreads();

    // ---- epilogue 2: x1 = acc + proj_b + x; LN2 -> c2 ----
    float psum[4][2], psq[4][2];
    #pragma unroll
    for (int mt = 0; mt < 4; mt++)
        #pragma unroll
        for (int h2 = 0; h2 < 2; h2++) { psum[mt][h2] = 0.0f; psq[mt][h2] = 0.0f; }

    #pragma unroll
    for (int mt = 0; mt < 4; mt++) {
        #pragma unroll
        for (int nt = 0; nt < 4; nt++) {
            int m = m0 + wm + mt * 16 + row;
            int n = wn + nt * 8 + 2 * col;
            float2 bv = *(const float2*)(proj_b + n);
            #pragma unroll
            for (int h2 = 0; h2 < 2; h2++) {
                int mg = m + h2 * 8;
                float vx = acc[mt][nt][h2 * 2 + 0] + bv.x;
                float vy = acc[mt][nt][h2 * 2 + 1] + bv.y;
                float2 e = *(const float2*)(x + (size_t)mg * CC + n);
                vx += e.x; vy += e.y;
                *(float2*)(x1 + (size_t)mg * CC + n) = make_float2(vx, vy);
                acc[mt][nt][h2 * 2 + 0] = vx;
                acc[mt][nt][h2 * 2 + 1] = vy;
                psum[mt][h2] += vx + vy;
                psq[mt][h2]  += vx * vx + vy * vy;
            }
        }
    }
    #pragma unroll
    for (int mt = 0; mt < 4; mt++)
        #pragma unroll
        for (int h2 = 0; h2 < 2; h2++) {
            #pragma unroll
            for (int o = 1; o <= 2; o <<= 1) {
                psum[mt][h2] += __shfl_xor_sync(0xffffffffu, psum[mt][h2], o);
                psq[mt][h2]  += __shfl_xor_sync(0xffffffffu, psq[mt][h2], o);
            }
        }
    float2* red = (float2*)sm;    // 128 rows x 4 warps
    int wg = warp & 3;
    if (col == 0) {
        #pragma unroll
        for (int mt = 0; mt < 4; mt++)
            #pragma unroll
            for (int h2 = 0; h2 < 2; h2++) {
                int lr = wm + mt * 16 + h2 * 8 + row;
                red[lr * 4 + wg] = make_float2(psum[mt][h2], psq[mt][h2]);
            }
    }
    __syncthreads();
    #pragma unroll
    for (int mt = 0; mt < 4; mt++) {
        #pragma unroll
        for (int h2 = 0; h2 < 2; h2++) {
            int lr = wm + mt * 16 + h2 * 8 + row;
            float s = 0.0f, qq = 0.0f;
            #pragma unroll
            for (int w2 = 0; w2 < 4; w2++) {
                float2 p = red[lr * 4 + w2];
                s += p.x; qq += p.y;
            }
            float mu = s * (1.0f / 128.0f);
            float var = qq * (1.0f / 128.0f) - mu * mu;
            float rr = rsqrtf(var + 1e-5f);
            int mg = m0 + lr;
            #pragma unroll
            for (int nt = 0; nt < 4; nt++) {
                int n = wn + nt * 8 + 2 * col;
                float2 gv = *(const float2*)(ln2g + n);
                float2 bv2 = *(const float2*)(ln2b + n);
                float ox = (acc[mt][nt][h2 * 2 + 0] - mu) * rr * gv.x + bv2.x;
                float oy = (acc[mt][nt][h2 * 2 + 1] - mu) * rr * gv.y + bv2.y;
                *(bf162*)(c2out + (size_t)mg * CC + n) = __floats2bfloat162_rn(ox, oy);
            }
        }
    }
}

// ======== fused MLP: hid = gelu(c2@fc1+b) in smem; out = x1 + hid@fc2 + b ========
__global__ void __launch_bounds__(256, 1)
mlp_fused(const bf16* __restrict__ c2,
          const bf16* __restrict__ fc1t,
          const bf16* __restrict__ fc2t,
          const float* __restrict__ fc1_b,
          const float* __restrict__ fc2_b,
          const float* __restrict__ x1,
          float* __restrict__ out)
{
    extern __shared__ uint32_t dsm[];
    const uint32_t sH = smem_u32(dsm);            // hid: 128 x 260 words
    const uint32_t sA = sH + 33280 * 4;           // A staging [2][128][20]
    const uint32_t sB = sA + 5120 * 4;            // B staging [2][128][20]

    const int tid  = threadIdx.x;
    const int lane = tid & 31, warp = tid >> 5;
    const int row  = lane >> 2, col = lane & 3;
    const int g8   = lane >> 3, r8 = lane & 7;
    const int wm   = (warp >> 2) * 64;
    const int wn   = (warp & 3) * 32;
    const int m0   = blockIdx.x * 128;

    const bf16* Ab = c2 + (size_t)m0 * CC;
    const int r_ld = tid >> 2, s_ld = tid & 3;

    // ---- stage 1: 4 n-chunks of fc1 + gelu -> hid smem ----
    for (int nc4 = 0; nc4 < 4; nc4++) {
        const bf16* Bb = fc1t + (size_t)(nc4 * 128) * CC;
        float acc[4][4][4];
        #pragma unroll
        for (int i = 0; i < 4; i++)
            #pragma unroll
            for (int j = 0; j < 4; j++)
                #pragma unroll
                for (int r = 0; r < 4; r++) acc[i][j][r] = 0.0f;

        auto load1 = [&](int kc, int buf) {
            #pragma unroll
            for (int t = 0; t < 2; t++) {
                int r = r_ld + t * 64;
                cp16(sA + (uint32_t)((((buf * 128 + r) * 20) + s_ld * 4) * 4),
                     Ab + (size_t)r * CC + kc + s_ld * 8);
                cp16(sB + (uint32_t)((((buf * 128 + r) * 20) + s_ld * 4) * 4),
                     Bb + (size_t)r * CC + kc + s_ld * 8);
            }
            asm volatile("cp.async.commit_group;" ::: "memory");
        };
        load1(0, 0);
        for (int i = 0; i < 4; i++) {
            int b = i & 1;
            if (i + 1 < 4) {
                load1((i + 1) * 32, b ^ 1);
                asm volatile("cp.async.wait_group 1;" ::: "memory");
            } else {
                asm volatile("cp.async.wait_group 0;" ::: "memory");
            }
            __syncthreads();
            #pragma unroll
            for (int kk = 0; kk < 2; kk++) {
                const int wo = kk * 8;
                uint32_t af[4][4], bq[2][4];
                #pragma unroll
                for (int mt = 0; mt < 4; mt++) {
                    int ar = wm + mt * 16 + (g8 & 1) * 8 + r8;
                    ldsm_x4(af[mt], sA + (uint32_t)((((b * 128 + ar) * 20) + wo + (g8 >> 1) * 4) * 4));
                }
                #pragma unroll
                for (int p = 0; p < 2; p++) {
                    int br = wn + p * 16 + (g8 >> 1) * 8 + r8;
                    ldsm_x4(bq[p], sB + (uint32_t)((((b * 128 + br) * 20) + wo + (g8 & 1) * 4) * 4));
                }
                #pragma unroll
                for (int mt = 0; mt < 4; mt++)
                    #pragma unroll
                    for (int nt = 0; nt < 4; nt++)
                        mma_bf16(acc[mt][nt], af[mt], &bq[nt >> 1][(nt & 1) * 2]);
            }
            __syncthreads();
        }
        // epilogue: gelu -> hid smem
        #pragma unroll
        for (int mt = 0; mt < 4; mt++) {
            #pragma unroll
            for (int nt = 0; nt < 4; nt++) {
                int ml = wm + mt * 16 + row;
                int n = wn + nt * 8 + 2 * col;
                float2 fb = *(const float2*)(fc1_b + nc4 * 128 + n);
                #pragma unroll
                for (int h2 = 0; h2 < 2; h2++) {
                    int mgl = ml + h2 * 8;
                    float ox = gelu_f(acc[mt][nt][h2 * 2 + 0] + fb.x);
                    float oy = gelu_f(acc[mt][nt][h2 * 2 + 1] + fb.y);
                    bf162 pv = __floats2bfloat162_rn(ox, oy);
                    dsm[mgl * 260 + nc4 * 64 + (n >> 1)] = *(uint32_t*)&pv;
                }
            }
        }
    }
    __syncthreads();

    // ---- stage 2: out = hid @ fc2T + fc2_b + x1  (K=512) ----
    float acc[4][4][4];
    #pragma unroll
    for (int i = 0; i < 4; i++)
        #pragma unroll
        for (int j = 0; j < 4; j++)
            #pragma unroll
            for (int r = 0; r < 4; r++) acc[i][j][r] = 0.0f;

    auto load2 = [&](int kc, int buf) {
        #pragma unroll
        for (int t = 0; t < 2; t++) {
            int r = r_ld + t * 64;
            cp16(sB + (uint32_t)((((buf * 128 + r) * 20) + s_ld * 4) * 4),
                 fc2t + (size_t)r * 512 + kc + s_ld * 8);
        }
        asm volatile("cp.async.commit_group;" ::: "memory");
    };
    load2(0, 0);
    for (int c = 0; c < 16; c++) {
        int b = c & 1;
        if (c + 1 < 16) {
            load2((c + 1) * 32, b ^ 1);
            asm volatile("cp.async.wait_group 1;" ::: "memory");
        } else {
            asm volatile("cp.async.wait_group 0;" ::: "memory");
        }
        __syncthreads();
        #pragma unroll
        for (int kk = 0; kk < 2; kk++) {
            int s = c * 2 + kk;
            uint32_t af[4][4], bq[2][4];
            #pragma unroll
            for (int mt = 0; mt < 4; mt++) {
                int ar = wm + mt * 16 + (g8 & 1) * 8 + r8;
                ldsm_x4(af[mt], sH + (uint32_t)(((ar * 260) + 8 * s + (g8 >> 1) * 4) * 4));
            }
            #pragma unroll
            for (int p = 0; p < 2; p++) {
                int br = wn + p * 16 + (g8 >> 1) * 8 + r8;
                ldsm_x4(bq[p], sB + (uint32_t)((((b * 128 + br) * 20) + kk * 8 + (g8 & 1) * 4) * 4));
            }
            #pragma unroll
            for (int mt = 0; mt < 4; mt++)
                #pragma unroll
                for (int nt = 0; nt < 4; nt++)
                    mma_bf16(acc[mt][nt], af[mt], &bq[nt >> 1][(nt & 1) * 2]);
        }
        __syncthreads();
    }

    #pragma unroll
    for (int mt = 0; mt < 4; mt++) {
        #pragma unroll
        for (int nt = 0; nt < 4; nt++) {
            int m = m0 + wm + mt * 16 + row;
            int n = wn + nt * 8 + 2 * col;
            float2 bv = *(const float2*)(fc2_b + n);
            #pragma unroll
            for (int h2 = 0; h2 < 2; h2++) {
                int mg = m + h2 * 8;
                float2 e = *(const float2*)(x1 + (size_t)mg * CC + n);
                float ox = acc[mt][nt][h2 * 2 + 0] + bv.x + e.x;
                float oy = acc[mt][nt][h2 * 2 + 1] + bv.y + e.y;
                *(float2*)(out + (size_t)mg * CC + n) = make_float2(ox, oy);
            }
        }
    }
}

// ------------- fused weight pack (transpose) to bf16 [N][K] -------------
__global__ void pack_all(const float* __restrict__ f_w, const float* __restrict__ h_w,
                         const float* __restrict__ proj_w, const float* __restrict__ fc1_w,
                         const float* __restrict__ fc2_w, bf16* __restrict__ wt)
{
    int idx = blockIdx.x * 256 + threadIdx.x;
    if (idx >= 196608) return;
    float v;
    if (idx < 32768) {
        int n = idx >> 7, k = idx & 127;
        v = f_w[k * FWLD + n];
    } else if (idx < 49152) {
        int j = idx - 32768; int n = j >> 7, k = j & 127;
        v = h_w[k * 128 + n];
    } else if (idx < 65536) {
        int j = idx - 49152; int n = j >> 7, k = j & 127;
        v = proj_w[k * 128 + n];
    } else if (idx < 131072) {
        int j = idx - 65536; int n = j >> 7, k = j & 127;
        v = fc1_w[k * 512 + n];
    } else {
        int j = idx - 131072; int n = j / 512, k = j % 512;
        v = fc2_w[k * 128 + n];
    }
    wt[idx] = __float2bfloat16(v);
}

// ---------------- LayerNorm + fused gates GEMV, grid-stride ----------------
__global__ void ln_gates_kernel(const float* __restrict__ x,
                                const float* __restrict__ g,
                                const float* __restrict__ b,
                                bf16* __restrict__ y,
                                const float* __restrict__ fw,
                                const float* __restrict__ fb,
                                float* __restrict__ gates)
{
    const int lane = threadIdx.x & 31;
    const int gwarp = (blockIdx.x * blockDim.x + threadIdx.x) >> 5;
    const int nwarp = (gridDim.x * blockDim.x) >> 5;

    float4 gg = ((const float4*)g)[lane];
    float4 bb = ((const float4*)b)[lane];
    float w[4][4], fbs[4];
    int k0 = lane * 4;
    #pragma unroll
    for (int c = 0; c < 4; c++)
        #pragma unroll
        for (int j = 0; j < 4; j++)
            w[c][j] = fw[(k0 + c) * FWLD + 256 + j];
    #pragma unroll
    for (int j = 0; j < 4; j++) fbs[j] = fb[256 + j];

    for (int tok = gwarp; tok < MM; tok += nwarp) {
        float4 v = ((const float4*)(x + (size_t)tok * CC))[lane];
        float s = v.x + v.y + v.z + v.w;
        #pragma unroll
        for (int o = 16; o; o >>= 1) s += __shfl_xor_sync(0xffffffffu, s, o);
        float mu = s * (1.0f / CC);
        float dx = v.x - mu, dy = v.y - mu, dz = v.z - mu, dw = v.w - mu;
        float s2 = dx*dx + dy*dy + dz*dz + dw*dw;
        #pragma unroll
        for (int o = 16; o; o >>= 1) s2 += __shfl_xor_sync(0xffffffffu, s2, o);
        float r = rsqrtf(s2 * (1.0f / CC) + 1e-5f);
        float y0 = dx * r * gg.x + bb.x;
        float y1 = dy * r * gg.y + bb.y;
        float y2v = dz * r * gg.z + bb.z;
        float y3 = dw * r * gg.w + bb.w;
        bf162 p0 = __floats2bfloat162_rn(y0, y1);
        bf162 p1 = __floats2bfloat162_rn(y2v, y3);
        uint2 u;
        u.x = *(uint32_t*)&p0; u.y = *(uint32_t*)&p1;
        ((uint2*)(y + (size_t)tok * CC))[lane] = u;

        float sg[4];
        #pragma unroll
        for (int j = 0; j < 4; j++) {
            sg[j] = y0 * w[0][j] + y1 * w[1][j] + y2v * w[2][j] + y3 * w[3][j];
            #pragma unroll
            for (int o = 16; o; o >>= 1) sg[j] += __shfl_xor_sync(0xffffffffu, sg[j], o);
        }
        if (lane == 0) {
            float4 gv = make_float4(sg[0] + fbs[0], sg[1] + fbs[1],
                                    sg[2] + fbs[2], sg[3] + fbs[3]);
            *(float4*)(gates + (size_t)tok * 4) = gv;
        }
    }
}

// ---------------- depthwise conv (channel-pair vectorized, TW=8) ----------------
template<int KS, int MODE>
__global__ void dwconv_kernel(const bf16* __restrict__ in,
                              const float* __restrict__ kern,
                              const float* __restrict__ gates,
                              bf16* __restrict__ out,
                              bf16* __restrict__ ctxall)
{
    constexpr int P = KS / 2, TW = 8, IW = TW + KS - 1;
    int cp = threadIdx.x;
    int blk = blockIdx.x;
    int wt = blk % (WW / TW);
    int rem = blk / (WW / TW);
    int h = rem % HH;
    int b = rem / HH;
    int w0 = wt * TW;

    float2 kw[KS * KS];
    #pragma unroll
    for (int i = 0; i < KS * KS; i++)
        kw[i] = make_float2(kern[i * CC + 2 * cp], kern[i * CC + 2 * cp + 1]);

    float2 acc[TW];
    #pragma unroll
    for (int o = 0; o < TW; o++) acc[o] = make_float2(0.0f, 0.0f);
    float2 center[TW];

    const bf162* base = (const bf162*)in + (size_t)b * LL * 64 + cp;
    #pragma unroll
    for (int kh = 0; kh < KS; kh++) {
        int ih = h + kh - P;
        if (ih < 0 || ih >= HH) continue;
        float2 inv[IW];
        #pragma unroll
        for (int i = 0; i < IW; i++) {
            int iw = w0 - P + i;
            inv[i] = (iw >= 0 && iw < WW)
                   ? __bfloat1622float2(base[((size_t)ih * WW + iw) * 64])
                   : make_float2(0.0f, 0.0f);
        }
        if (MODE == 1 && kh == P) {
            #pragma unroll
            for (int o = 0; o < TW; o++) center[o] = inv[o + P];
        }
        #pragma unroll
        for (int kx = 0; kx < KS; kx++) {
            float2 wv = kw[kh * KS + kx];
            #pragma unroll
            for (int o = 0; o < TW; o++) {
                acc[o].x += inv[o + kx].x * wv.x;
                acc[o].y += inv[o + kx].y * wv.y;
            }
        }
    }
    size_t opix = (size_t)b * LL + (size_t)h * WW + w0;
    bf162* outp = (bf162*)out;
    bf162* cap  = (bf162*)ctxall;
    #pragma unroll
    for (int o = 0; o < TW; o++) {
        float vx = gelu_f(acc[o].x), vy = gelu_f(acc[o].y);
        outp[(opix + o) * 64 + cp] = __floats2bfloat162_rn(vx, vy);
        if (MODE == 1) {
            float g0 = gates[(opix + o) * 4 + 0];
            float g1 = gates[(opix + o) * 4 + 1];
            cap[(opix + o) * 64 + cp] = __floats2bfloat162_rn(
                center[o].x * g0 + vx * g1, center[o].y * g0 + vy * g1);
        } else if (MODE == 2) {
            float g2 = gates[(opix + o) * 4 + 2];
            float2 cur = __bfloat1622float2(cap[(opix + o) * 64 + cp]);
            cap[(opix + o) * 64 + cp] = __floats2bfloat162_rn(
                cur.x + vx * g2, cur.y + vy * g2);
        }
    }
}

// ---------------- global mean pool + gelu ----------------
__global__ void pool_kernel(const bf16* __restrict__ ctx, float* __restrict__ pool)
{
    __shared__ float sm[8][128];
    int b = blockIdx.x;
    int tid = threadIdx.x;
    int c = tid & 127, s = tid >> 7;
    const bf16* p = ctx + ((size_t)b * LL + (size_t)s * (LL / 8)) * CC + c;
    float acc = 0.0f;
    for (int i = 0; i < LL / 8; i++) acc += __bfloat162float(p[(size_t)i * CC]);
    sm[s][c] = acc;
    __syncthreads();
    if (s == 0) {
        float t = 0.0f;
        #pragma unroll
        for (int k = 0; k < 8; k++) t += sm[k][c];
        pool[b * CC + c] = gelu_f(t * (1.0f / LL));
    }
}

// ---------------- P2[b,n] = pool[b,:] @ h_w[:,n] ----------------
__global__ void p2_kernel(const float* __restrict__ pool,
                          const float* __restrict__ h_w,
                          float* __restrict__ P2)
{
    __shared__ float prow[128];
    int b = blockIdx.x, n = threadIdx.x;
    prow[n] = pool[b * CC + n];
    __syncthreads();
    float s = 0.0f;
    #pragma unroll 8
    for (int k = 0; k < CC; k++) s += prow[k] * h_w[k * CC + n];
    P2[b * CC + n] = s;
}

// ---------------- launch ----------------
extern "C" void kernel_launch(void* const* d_in, const int* in_sizes, int n_in,
                              void* d_out, int out_size)
{
    const float* x      = (const float*)d_in[0];
    const float* f_w    = (const float*)d_in[1];
    const float* f_b    = (const float*)d_in[2];
    const float* k0     = (const float*)d_in[3];
    const float* k1     = (const float*)d_in[4];
    const float* k2     = (const float*)d_in[5];
    const float* h_w    = (const float*)d_in[6];
    const float* h_b    = (const float*)d_in[7];
    const float* proj_w = (const float*)d_in[8];
    const float* proj_b = (const float*)d_in[9];
    const float* ln1_g  = (const float*)d_in[10];
    const float* ln1_b  = (const float*)d_in[11];
    const float* ln2_g  = (const float*)d_in[12];
    const float* ln2_b  = (const float*)d_in[13];
    const float* fc1_w  = (const float*)d_in[14];
    const float* fc1_b  = (const float*)d_in[15];
    const float* fc2_w  = (const float*)d_in[16];
    const float* fc2_b  = (const float*)d_in[17];
    float* out = (float*)d_out;

    bf16 *y, *q, *c0, *c1, *call, *c2, *wt;
    float *gts, *pl, *p2, *x1;
    cudaGetSymbolAddress((void**)&y,    g_y);
    cudaGetSymbolAddress((void**)&q,    g_q);
    cudaGetSymbolAddress((void**)&c0,   g_c0);
    cudaGetSymbolAddress((void**)&c1,   g_c1);
    cudaGetSymbolAddress((void**)&call, g_call);
    cudaGetSymbolAddress((void**)&c2,   g_c2);
    cudaGetSymbolAddress((void**)&gts,  g_gates);
    cudaGetSymbolAddress((void**)&pl,   g_pool);
    cudaGetSymbolAddress((void**)&p2,   g_p2);
    cudaGetSymbolAddress((void**)&x1,   g_x1);
    cudaGetSymbolAddress((void**)&wt,   g_wt);

    const int MBLK = MM / 128;                 // 1568
    const int conv_grid = BB * HH * (WW / 8);  // 25088
    const int MLP_SMEM = 43520 * 4;            // 174080 B

    cudaFuncSetAttribute(mlp_fused, cudaFuncAttributeMaxDynamicSharedMemorySize, MLP_SMEM);

    // 1. pack weights
    pack_all<<<768, 256>>>(f_w, h_w, proj_w, fc1_w, fc2_w, wt);
    // 2. y = LN1(x) + fused gates
    ln_gates_kernel<<<3136, 256>>>(x, ln1_g, ln1_b, y, f_w, f_b, gts);
    // 3. fused q|ctx GEMM (N=256)
    bf_gemm_qc<<<dim3(MBLK, 2), 256>>>(y, wt + WT_QC, f_b, q, c0);
    // 4-6. focal levels (ctxall chain fused into conv5/conv7)
    dwconv_kernel<3, 0><<<conv_grid, 64>>>(c0, k0, gts, c1, call);
    dwconv_kernel<5, 1><<<conv_grid, 64>>>(c1, k1, gts, c0, call);
    dwconv_kernel<7, 2><<<conv_grid, 64>>>(c0, k2, gts, c1, call);
    // 7. pool = gelu(mean(ctx3))
    pool_kernel<<<BB, 1024>>>(c1, pl);
    // 8. P2 = pool @ h_w
    p2_kernel<<<BB, 128>>>(pl, h_w, p2);
    // 9. fused: y2=(call@H+h_b+g3*P2)*q -> x1 = x + y2@proj + proj_b -> c2 = LN2(x1)
    hp_fused<<<MBLK, 256>>>(call, wt + WT_H, wt + WT_PROJ, h_b, q, gts, p2,
                            x, proj_b, x1, ln2_g, ln2_b, c2);
    // 10. fused MLP: out = x1 + gelu(c2@fc1+b)@fc2 + b
    mlp_fused<<<MBLK, 256, MLP_SMEM>>>(c2, wt + WT_FC1, wt + WT_FC2,
                                       fc1_b, fc2_b, x1, out);
}